// round 13
// baseline (speedup 1.0000x reference)
#include <cuda_runtime.h>
#include <cuda_fp16.h>
#include <cstdint>

#define NMAX 400000
#define EMAX 1600000
#define GMAX 4096
#define HD   128
#define CHUNK 1024

#define APAD 40    // smem row stride in halves (32 data + 8 pad); conflict-free for LDSM

// -------- device scratch --------
__device__ int    g_counts [NMAX];
__device__ int    g_rowptr [NMAX + 1];
__device__ int    g_cursor [NMAX];
__device__ int    g_colidx [EMAX];
__device__ int    g_bsum   [512];
__device__ int    g_boff   [512];
__device__ float  g_dinv   [NMAX];
__device__ __half g_xs     [(size_t)NMAX * 80];    // x*dinv fp16, stride 80 (cols 78,79 = 0)
__device__ __half g_ax     [(size_t)NMAX * 96];    // layer-0 agg out, stride 96 (cols 78..95 = 0)
__device__ __half g_hh     [(size_t)NMAX * 128];   // h0*dinv after layer0 GEMM
__device__ __half g_ah     [(size_t)NMAX * 128];   // layer-1 agg out
__device__ __half g_w0t    [128 * 96];             // W0^T fp16 [n][k], k padded to 96
__device__ __half g_w1t    [128 * 128];            // W1^T fp16 [n][k]
__device__ float  g_pool   [(size_t)GMAX * HD];
__device__ float  g_ff     [(size_t)GMAX * 256];

// unpack uint2 (4 halves) and accumulate into float4
__device__ __forceinline__ void acc_u2(uint2 v, float4& a) {
    float2 f0 = __half22float2(*reinterpret_cast<__half2*>(&v.x));
    float2 f1 = __half22float2(*reinterpret_cast<__half2*>(&v.y));
    a.x += f0.x; a.y += f0.y; a.z += f1.x; a.w += f1.y;
}

__device__ __forceinline__ uint2 pack_f4(float4 a, float s) {
    uint2 o;
    __half2 h0 = __floats2half2_rn(a.x * s, a.y * s);
    __half2 h1 = __floats2half2_rn(a.z * s, a.w * s);
    o.x = *reinterpret_cast<uint32_t*>(&h0);
    o.y = *reinterpret_cast<uint32_t*>(&h1);
    return o;
}

__device__ __forceinline__ void ldsm_x4(uint32_t& r0, uint32_t& r1, uint32_t& r2, uint32_t& r3,
                                        uint32_t addr) {
    asm volatile("ldmatrix.sync.aligned.m8n8.x4.shared.b16 {%0,%1,%2,%3}, [%4];"
                 : "=r"(r0), "=r"(r1), "=r"(r2), "=r"(r3) : "r"(addr));
}

// ---------------- degree / CSR build ----------------
__global__ void count_deg_kernel(const int* __restrict__ dst, int* counts, int E) {
    int e = blockIdx.x * blockDim.x + threadIdx.x;
    if (e < E) atomicAdd(&counts[dst[e]], 1);
}

__global__ void scan_chunk_sum(const int* __restrict__ counts, int* bsum,
                               float* __restrict__ dinv, int N) {
    __shared__ int sh[256];
    int base = blockIdx.x * CHUNK;
    int s = 0;
    for (int i = threadIdx.x; i < CHUNK; i += 256) {
        int g = base + i;
        int c = (g < N) ? counts[g] : 0;
        s += c;
        if (g < N) dinv[g] = rsqrtf((float)c + 1.0f);
    }
    sh[threadIdx.x] = s; __syncthreads();
    for (int o = 128; o > 0; o >>= 1) {
        if (threadIdx.x < o) sh[threadIdx.x] += sh[threadIdx.x + o];
        __syncthreads();
    }
    if (threadIdx.x == 0) bsum[blockIdx.x] = sh[0];
}

__global__ void scan_bsum(const int* __restrict__ bsum, int* boff, int NB) {
    __shared__ int sh[512];
    int v = (threadIdx.x < NB) ? bsum[threadIdx.x] : 0;
    sh[threadIdx.x] = v; __syncthreads();
    for (int o = 1; o < 512; o <<= 1) {
        int t = (threadIdx.x >= o) ? sh[threadIdx.x - o] : 0;
        __syncthreads();
        sh[threadIdx.x] += t;
        __syncthreads();
    }
    if (threadIdx.x < NB) boff[threadIdx.x] = sh[threadIdx.x] - v;  // exclusive
}

__global__ void scan_final(const int* __restrict__ counts, const int* __restrict__ boff,
                           int* rowptr, int* cursor, int N) {
    __shared__ int sh[CHUNK];
    int g = blockIdx.x * CHUNK + threadIdx.x;
    int v = (g < N) ? counts[g] : 0;
    sh[threadIdx.x] = v; __syncthreads();
    for (int o = 1; o < CHUNK; o <<= 1) {
        int t = (threadIdx.x >= o) ? sh[threadIdx.x - o] : 0;
        __syncthreads();
        sh[threadIdx.x] += t;
        __syncthreads();
    }
    if (g < N) {
        int excl = boff[blockIdx.x] + sh[threadIdx.x] - v;
        rowptr[g] = excl;
        cursor[g] = excl;
        if (g == N - 1) rowptr[N] = boff[blockIdx.x] + sh[threadIdx.x];
    }
}

__global__ void fill_csr_kernel(const int* __restrict__ src, const int* __restrict__ dst,
                                int* cursor, int* colidx, int E) {
    int e = blockIdx.x * blockDim.x + threadIdx.x;
    if (e < E) {
        int d = dst[e];
        int p = atomicAdd(&cursor[d], 1);
        colidx[p] = src[e];
    }
}

// ---------------- conversions ----------------
__global__ void conv_x_kernel(const float* __restrict__ x, const float* __restrict__ dinv,
                              __half2* __restrict__ xs2, int N) {
    int i = blockIdx.x * blockDim.x + threadIdx.x;   // over N*40 half2
    if (i >= N * 40) return;
    int n = i / 40;
    int c = i - n * 40;
    float dd = __ldg(&dinv[n]);
    float v0 = (2 * c     < 78) ? x[(size_t)n * 78 + 2 * c]     * dd : 0.0f;
    float v1 = (2 * c + 1 < 78) ? x[(size_t)n * 78 + 2 * c + 1] * dd : 0.0f;
    xs2[i] = __floats2half2_rn(v0, v1);
}

__global__ void conv_w_kernel(const float* __restrict__ W0, const float* __restrict__ W1,
                              __half* __restrict__ W0t, __half* __restrict__ W1t) {
    int i = blockIdx.x * blockDim.x + threadIdx.x;
    if (i < 128 * 96) {
        int n = i / 96;
        int k = i - n * 96;
        W0t[i] = (k < 78) ? __float2half_rn(W0[(size_t)k * 128 + n]) : __float2half_rn(0.0f);
    } else if (i < 128 * 96 + 128 * 128) {
        int j = i - 128 * 96;
        int n = j >> 7;
        int k = j & 127;
        W1t[j] = __float2half_rn(W1[(size_t)k * 128 + n]);
    }
}

// ---------------- agg0: ax[d] = h16( dinv[d]*(xs[d] + sum_{s} xs[s]) ), xs already *dinv ----------------
__global__ void agg0_kernel(const uint2* __restrict__ xsv, const int* __restrict__ rowptr,
                            const int* __restrict__ colidx, const float* __restrict__ dinv,
                            uint2* __restrict__ axv, int N)
{
    int w = (blockIdx.x * blockDim.x + threadIdx.x) >> 5;
    int lane = threadIdx.x & 31;
    if (w >= N) return;
    const bool act = lane < 20;

    float4 a = make_float4(0.f, 0.f, 0.f, 0.f);
    if (act) acc_u2(__ldg(&xsv[(size_t)w * 20 + lane]), a);

    int s0 = __ldg(&rowptr[w]);
    int s1 = __ldg(&rowptr[w + 1]);
    int e = s0;
    for (; e + 4 <= s1; e += 4) {
        int i0 = __ldg(&colidx[e + 0]);
        int i1 = __ldg(&colidx[e + 1]);
        int i2 = __ldg(&colidx[e + 2]);
        int i3 = __ldg(&colidx[e + 3]);
        if (act) {
            uint2 u0 = __ldg(&xsv[(size_t)i0 * 20 + lane]);
            uint2 u1 = __ldg(&xsv[(size_t)i1 * 20 + lane]);
            uint2 u2 = __ldg(&xsv[(size_t)i2 * 20 + lane]);
            uint2 u3 = __ldg(&xsv[(size_t)i3 * 20 + lane]);
            acc_u2(u0, a); acc_u2(u1, a); acc_u2(u2, a); acc_u2(u3, a);
        }
    }
    for (; e < s1; e++) {
        int s = __ldg(&colidx[e]);
        if (act) acc_u2(__ldg(&xsv[(size_t)s * 20 + lane]), a);
    }

    float dd = __ldg(&dinv[w]);
    if (act)
        axv[(size_t)w * 24 + lane] = pack_f4(a, dd);
    else if (lane < 24)
        axv[(size_t)w * 24 + lane] = make_uint2(0u, 0u);   // pad halves 80..95
}

// ---------------- agg1 (128-dim): ah[d] = h16( dinv[d]*(hs[d] + sum_{s} hs[s]) ), hs = h0*dinv ----------------
__global__ void agg1_kernel(const uint2* __restrict__ hsv, const int* __restrict__ rowptr,
                            const int* __restrict__ colidx, const float* __restrict__ dinv,
                            uint2* __restrict__ ahv, int N)
{
    int w = (blockIdx.x * blockDim.x + threadIdx.x) >> 5;
    int lane = threadIdx.x & 31;
    if (w >= N) return;

    float4 a = make_float4(0.f, 0.f, 0.f, 0.f);
    acc_u2(__ldg(&hsv[(size_t)w * 32 + lane]), a);

    int s0 = __ldg(&rowptr[w]);
    int s1 = __ldg(&rowptr[w + 1]);
    int e = s0;
    for (; e + 4 <= s1; e += 4) {
        int i0 = __ldg(&colidx[e + 0]);
        int i1 = __ldg(&colidx[e + 1]);
        int i2 = __ldg(&colidx[e + 2]);
        int i3 = __ldg(&colidx[e + 3]);
        uint2 u0 = __ldg(&hsv[(size_t)i0 * 32 + lane]);
        uint2 u1 = __ldg(&hsv[(size_t)i1 * 32 + lane]);
        uint2 u2 = __ldg(&hsv[(size_t)i2 * 32 + lane]);
        uint2 u3 = __ldg(&hsv[(size_t)i3 * 32 + lane]);
        acc_u2(u0, a); acc_u2(u1, a); acc_u2(u2, a); acc_u2(u3, a);
    }
    for (; e < s1; e++) {
        int s = __ldg(&colidx[e]);
        acc_u2(__ldg(&hsv[(size_t)s * 32 + lane]), a);
    }

    float dd = __ldg(&dinv[w]);
    ahv[(size_t)w * 32 + lane] = pack_f4(a, dd);
}

// ---------------- shared MMA inner chunk (ldmatrix fragment loads) ----------------
// Loads A/B fragments for one 16-wide K chunk at ks and accumulates 4x4 MMAs.
__device__ __forceinline__ void mma_chunk(const __half* As, const __half* Bs,
                                          int wm, int wn, int ks, int lane,
                                          float c[4][4][4])
{
    const int rl  = lane & 15;            // A row within 16
    const int kof = (lane >> 4) * 8;      // A k-offset 0/8
    uint32_t a[4][4];
#pragma unroll
    for (int mf = 0; mf < 4; mf++) {
        uint32_t addr = (uint32_t)__cvta_generic_to_shared(
            &As[(wm + mf * 16 + rl) * APAD + ks + kof]);
        ldsm_x4(a[mf][0], a[mf][1], a[mf][2], a[mf][3], addr);
    }
    uint32_t b[4][2];
    const int g   = lane >> 3;
    const int brl = (g >> 1) * 8 + (lane & 7);   // B n-row within 16
    const int bkf = (g & 1) * 8;                 // B k-offset 0/8
#pragma unroll
    for (int p = 0; p < 2; p++) {
        uint32_t addr = (uint32_t)__cvta_generic_to_shared(
            &Bs[(wn + p * 16 + brl) * APAD + ks + bkf]);
        ldsm_x4(b[2 * p][0], b[2 * p][1], b[2 * p + 1][0], b[2 * p + 1][1], addr);
    }
#pragma unroll
    for (int mf = 0; mf < 4; mf++)
#pragma unroll
        for (int nf = 0; nf < 4; nf++) {
            asm volatile(
                "mma.sync.aligned.m16n8k16.row.col.f32.f16.f16.f32 "
                "{%0,%1,%2,%3}, {%4,%5,%6,%7}, {%8,%9}, {%0,%1,%2,%3};"
                : "+f"(c[mf][nf][0]), "+f"(c[mf][nf][1]),
                  "+f"(c[mf][nf][2]), "+f"(c[mf][nf][3])
                : "r"(a[mf][0]), "r"(a[mf][1]), "r"(a[mf][2]), "r"(a[mf][3]),
                  "r"(b[nf][0]), "r"(b[nf][1]));
        }
}

// ---------------- fp16 tensor-core GEMM (layer 0): hh = h16(relu(A@Wt^T + bias) * rowscale) ----------------
__global__ void __launch_bounds__(256, 2)
gemm_h_kernel(const __half* __restrict__ A, const __half* __restrict__ Wt,
              const float* __restrict__ bias, const float* __restrict__ rowscale,
              __half* __restrict__ out, int K)
{
    __shared__ __half As[2][128 * APAD];
    __shared__ __half Bs[2][128 * APAD];

    const int tid  = threadIdx.x;
    const int row0 = blockIdx.x * 128;
    const int lane = tid & 31;
    const int wid  = tid >> 5;
    const int gid  = lane >> 2;
    const int tig  = lane & 3;
    const int wm   = (wid & 1) * 64;
    const int wn   = (wid >> 1) * 32;

    float c[4][4][4];
#pragma unroll
    for (int i = 0; i < 4; i++)
#pragma unroll
        for (int j = 0; j < 4; j++)
#pragma unroll
            for (int r = 0; r < 4; r++) c[i][j][r] = 0.0f;

    const int KC = K >> 5;

    auto issue = [&](int kc, int buf) {
        const int k0 = kc << 5;
#pragma unroll
        for (int rpt = 0; rpt < 2; rpt++) {
            int i = tid + rpt * 256;
            int m = i >> 2, ch = i & 3;
            const __half* src = A + (size_t)(row0 + m) * K + k0 + ch * 8;
            uint32_t dst = (uint32_t)__cvta_generic_to_shared(&As[buf][m * APAD + ch * 8]);
            asm volatile("cp.async.cg.shared.global [%0], [%1], 16;" :: "r"(dst), "l"(src));
        }
#pragma unroll
        for (int rpt = 0; rpt < 2; rpt++) {
            int i = tid + rpt * 256;
            int n = i >> 2, ch = i & 3;
            const __half* src = Wt + (size_t)n * K + k0 + ch * 8;
            uint32_t dst = (uint32_t)__cvta_generic_to_shared(&Bs[buf][n * APAD + ch * 8]);
            asm volatile("cp.async.cg.shared.global [%0], [%1], 16;" :: "r"(dst), "l"(src));
        }
        asm volatile("cp.async.commit_group;" ::: "memory");
    };

    issue(0, 0);

    for (int kc = 0; kc < KC; kc++) {
        const int buf = kc & 1;
        asm volatile("cp.async.wait_group 0;" ::: "memory");
        __syncthreads();
        if (kc + 1 < KC) issue(kc + 1, buf ^ 1);

        mma_chunk(As[buf], Bs[buf], wm, wn, 0,  lane, c);
        mma_chunk(As[buf], Bs[buf], wm, wn, 16, lane, c);
        __syncthreads();
    }

    float bxv[4], byv[4];
#pragma unroll
    for (int nf = 0; nf < 4; nf++) {
        const int cc = wn + nf * 8 + 2 * tig;
        bxv[nf] = bias[cc];
        byv[nf] = bias[cc + 1];
    }
#pragma unroll
    for (int mf = 0; mf < 4; mf++) {
        const int r0 = row0 + wm + mf * 16 + gid;
        float rs0 = rowscale[r0], rs1 = rowscale[r0 + 8];
#pragma unroll
        for (int nf = 0; nf < 4; nf++) {
            const int cc = wn + nf * 8 + 2 * tig;
            __half2 v0 = __floats2half2_rn(fmaxf(c[mf][nf][0] + bxv[nf], 0.f) * rs0,
                                           fmaxf(c[mf][nf][1] + byv[nf], 0.f) * rs0);
            __half2 v1 = __floats2half2_rn(fmaxf(c[mf][nf][2] + bxv[nf], 0.f) * rs1,
                                           fmaxf(c[mf][nf][3] + byv[nf], 0.f) * rs1);
            *reinterpret_cast<__half2*>(&out[(size_t)r0 * 128 + cc]) = v0;
            *reinterpret_cast<__half2*>(&out[(size_t)(r0 + 8) * 128 + cc]) = v1;
        }
    }
}

// ---------------- fused layer-1 GEMM + global max pool ----------------
__global__ void __launch_bounds__(256, 2)
gemm_h_pool_kernel(const __half* __restrict__ A, const __half* __restrict__ Wt,
                   const float* __restrict__ bias, const int* __restrict__ batch,
                   float* __restrict__ pool, int K, int G)
{
    __shared__ __half As[2][128 * APAD];
    __shared__ __half Bs[2][128 * APAD];
    __shared__ unsigned int pool_s[4 * 128];   // up to 4 graph segments per 128-row block

    const int tid  = threadIdx.x;
    const int row0 = blockIdx.x * 128;
    const int lane = tid & 31;
    const int wid  = tid >> 5;
    const int gid  = lane >> 2;
    const int tig  = lane & 3;
    const int wm   = (wid & 1) * 64;
    const int wn   = (wid >> 1) * 32;

    for (int i = tid; i < 4 * 128; i += 256) pool_s[i] = 0u;

    float c[4][4][4];
#pragma unroll
    for (int i = 0; i < 4; i++)
#pragma unroll
        for (int j = 0; j < 4; j++)
#pragma unroll
            for (int r = 0; r < 4; r++) c[i][j][r] = 0.0f;

    const int KC = K >> 5;

    auto issue = [&](int kc, int buf) {
        const int k0 = kc << 5;
#pragma unroll
        for (int rpt = 0; rpt < 2; rpt++) {
            int i = tid + rpt * 256;
            int m = i >> 2, ch = i & 3;
            const __half* src = A + (size_t)(row0 + m) * K + k0 + ch * 8;
            uint32_t dst = (uint32_t)__cvta_generic_to_shared(&As[buf][m * APAD + ch * 8]);
            asm volatile("cp.async.cg.shared.global [%0], [%1], 16;" :: "r"(dst), "l"(src));
        }
#pragma unroll
        for (int rpt = 0; rpt < 2; rpt++) {
            int i = tid + rpt * 256;
            int n = i >> 2, ch = i & 3;
            const __half* src = Wt + (size_t)n * K + k0 + ch * 8;
            uint32_t dst = (uint32_t)__cvta_generic_to_shared(&Bs[buf][n * APAD + ch * 8]);
            asm volatile("cp.async.cg.shared.global [%0], [%1], 16;" :: "r"(dst), "l"(src));
        }
        asm volatile("cp.async.commit_group;" ::: "memory");
    };

    issue(0, 0);

    for (int kc = 0; kc < KC; kc++) {
        const int buf = kc & 1;
        asm volatile("cp.async.wait_group 0;" ::: "memory");
        __syncthreads();
        if (kc + 1 < KC) issue(kc + 1, buf ^ 1);

        mma_chunk(As[buf], Bs[buf], wm, wn, 0,  lane, c);
        mma_chunk(As[buf], Bs[buf], wm, wn, 16, lane, c);
        __syncthreads();
    }

    // epilogue: relu(acc+bias) -> per-segment smem max -> global atomicMax
    float bxv[4], byv[4];
#pragma unroll
    for (int nf = 0; nf < 4; nf++) {
        const int cc = wn + nf * 8 + 2 * tig;
        bxv[nf] = bias[cc];
        byv[nf] = bias[cc + 1];
    }
    const int gbase = __ldg(&batch[row0]);
#pragma unroll
    for (int mf = 0; mf < 4; mf++) {
        const int r0 = row0 + wm + mf * 16 + gid;
        const int seg0 = __ldg(&batch[r0]) - gbase;
        const int seg1 = __ldg(&batch[r0 + 8]) - gbase;
#pragma unroll
        for (int nf = 0; nf < 4; nf++) {
            const int cc = wn + nf * 8 + 2 * tig;
            float v00 = fmaxf(c[mf][nf][0] + bxv[nf], 0.f);
            float v01 = fmaxf(c[mf][nf][1] + byv[nf], 0.f);
            float v10 = fmaxf(c[mf][nf][2] + bxv[nf], 0.f);
            float v11 = fmaxf(c[mf][nf][3] + byv[nf], 0.f);
            atomicMax(&pool_s[seg0 * 128 + cc],     __float_as_uint(v00));
            atomicMax(&pool_s[seg0 * 128 + cc + 1], __float_as_uint(v01));
            atomicMax(&pool_s[seg1 * 128 + cc],     __float_as_uint(v10));
            atomicMax(&pool_s[seg1 * 128 + cc + 1], __float_as_uint(v11));
        }
    }
    __syncthreads();
    for (int i = tid; i < 4 * 128; i += 256) {
        int g = gbase + (i >> 7);
        unsigned int v = pool_s[i];
        if (g < G && v != 0u)
            atomicMax(reinterpret_cast<unsigned int*>(&pool[(size_t)g * 128 + (i & 127)]), v);
    }
}

// ---------------- FFMA GEMM for FF head (full fp32): out = relu(A@W + bias) ----------------
__global__ void __launch_bounds__(256, 2)
gemm_ff_kernel(const float* __restrict__ A, const float* __restrict__ W,
               const float* __restrict__ bias, float* __restrict__ out,
               int M, int K, int Nout)
{
    __shared__ float As[16 * 128];
    __shared__ float Bs[16 * 128];

    const int tid  = threadIdx.x;
    const int tx   = tid & 15;
    const int ty   = tid >> 4;
    const int row0 = blockIdx.x * 128;
    const int col0 = blockIdx.y * 128;

    float acc[8][8];
#pragma unroll
    for (int i = 0; i < 8; i++)
#pragma unroll
        for (int j = 0; j < 8; j++) acc[i][j] = 0.0f;

    const int KC = (K + 15) >> 4;
    for (int kc = 0; kc < KC; kc++) {
        const int k0 = kc << 4;
        for (int i = tid; i < 512; i += 256) {
            int m = i >> 2, kv = (i & 3) << 2;
            int row = row0 + m;
            float4 v = make_float4(0.f, 0.f, 0.f, 0.f);
            if (row < M && (k0 + kv) < K)
                v = *reinterpret_cast<const float4*>(&A[(size_t)row * K + k0 + kv]);
            As[(kv + 0) * 128 + m] = v.x;
            As[(kv + 1) * 128 + m] = v.y;
            As[(kv + 2) * 128 + m] = v.z;
            As[(kv + 3) * 128 + m] = v.w;
        }
        for (int i = tid; i < 512; i += 256) {
            int kk = i >> 5, n4 = (i & 31) << 2;
            float4 v = make_float4(0.f, 0.f, 0.f, 0.f);
            if ((k0 + kk) < K)
                v = *reinterpret_cast<const float4*>(&W[(size_t)(k0 + kk) * Nout + col0 + n4]);
            *reinterpret_cast<float4*>(&Bs[kk * 128 + n4]) = v;
        }
        __syncthreads();
#pragma unroll
        for (int kk = 0; kk < 16; kk++) {
            float4 a0 = *reinterpret_cast<const float4*>(&As[kk * 128 + ty * 8]);
            float4 a1 = *reinterpret_cast<const float4*>(&As[kk * 128 + ty * 8 + 4]);
            float4 b0 = *reinterpret_cast<const float4*>(&Bs[kk * 128 + tx * 8]);
            float4 b1 = *reinterpret_cast<const float4*>(&Bs[kk * 128 + tx * 8 + 4]);
            float av[8] = {a0.x, a0.y, a0.z, a0.w, a1.x, a1.y, a1.z, a1.w};
            float bv[8] = {b0.x, b0.y, b0.z, b0.w, b1.x, b1.y, b1.z, b1.w};
#pragma unroll
            for (int i = 0; i < 8; i++)
#pragma unroll
                for (int j = 0; j < 8; j++)
                    acc[i][j] += av[i] * bv[j];
        }
        __syncthreads();
    }

#pragma unroll
    for (int i = 0; i < 8; i++) {
        int row = row0 + ty * 8 + i;
        if (row >= M) break;
        const float4 b0 = *reinterpret_cast<const float4*>(&bias[col0 + tx * 8]);
        const float4 b1 = *reinterpret_cast<const float4*>(&bias[col0 + tx * 8 + 4]);
        float4 v0 = make_float4(fmaxf(acc[i][0] + b0.x, 0.f), fmaxf(acc[i][1] + b0.y, 0.f),
                                fmaxf(acc[i][2] + b0.z, 0.f), fmaxf(acc[i][3] + b0.w, 0.f));
        float4 v1 = make_float4(fmaxf(acc[i][4] + b1.x, 0.f), fmaxf(acc[i][5] + b1.y, 0.f),
                                fmaxf(acc[i][6] + b1.z, 0.f), fmaxf(acc[i][7] + b1.w, 0.f));
        float4* o = reinterpret_cast<float4*>(&out[(size_t)row * Nout + col0 + tx * 8]);
        o[0] = v0; o[1] = v1;
    }
}

// ---------------- launch ----------------
extern "C" void kernel_launch(void* const* d_in, const int* in_sizes, int n_in,
                              void* d_out, int out_size)
{
    const float* x     = (const float*)d_in[0];
    const int*   ei    = (const int*)d_in[1];
    const int*   batch = (const int*)d_in[2];
    const float* W0    = (const float*)d_in[3];
    const float* b0    = (const float*)d_in[4];
    const float* W1    = (const float*)d_in[5];
    const float* b1    = (const float*)d_in[6];
    const float* Wf0   = (const float*)d_in[7];
    const float* bf0   = (const float*)d_in[8];
    const float* Wf1   = (const float*)d_in[9];
    const float* bf1   = (const float*)d_in[10];
    float*       out   = (float*)d_out;

    const int F_IN = 78;
    const int N = in_sizes[0] / F_IN;
    const int E = in_sizes[1] / 2;
    const int G = out_size / HD;

    const int* src = ei;
    const int* dst = ei + E;

    int *p_counts, *p_rowptr, *p_cursor, *p_colidx, *p_bsum, *p_boff;
    float *p_dinv, *p_pool, *p_ff;
    __half *p_xs, *p_ax, *p_hh, *p_ah, *p_w0t, *p_w1t;
    cudaGetSymbolAddress((void**)&p_counts, g_counts);
    cudaGetSymbolAddress((void**)&p_rowptr, g_rowptr);
    cudaGetSymbolAddress((void**)&p_cursor, g_cursor);
    cudaGetSymbolAddress((void**)&p_colidx, g_colidx);
    cudaGetSymbolAddress((void**)&p_bsum,   g_bsum);
    cudaGetSymbolAddress((void**)&p_boff,   g_boff);
    cudaGetSymbolAddress((void**)&p_dinv,   g_dinv);
    cudaGetSymbolAddress((void**)&p_xs,     g_xs);
    cudaGetSymbolAddress((void**)&p_ax,     g_ax);
    cudaGetSymbolAddress((void**)&p_hh,     g_hh);
    cudaGetSymbolAddress((void**)&p_ah,     g_ah);
    cudaGetSymbolAddress((void**)&p_w0t,    g_w0t);
    cudaGetSymbolAddress((void**)&p_w1t,    g_w1t);
    cudaGetSymbolAddress((void**)&p_pool,   g_pool);
    cudaGetSymbolAddress((void**)&p_ff,     g_ff);

    const int TB = 256;
    int gE = (E + TB - 1) / TB;
    int NB = (N + CHUNK - 1) / CHUNK;
    int gW = (N * 32 + TB - 1) / TB;   // warp-per-node grids

    // ---- CSR build + norm ----
    cudaMemsetAsync(p_counts, 0, (size_t)N * sizeof(int));
    count_deg_kernel<<<gE, TB>>>(dst, p_counts, E);
    scan_chunk_sum<<<NB, 256>>>(p_counts, p_bsum, p_dinv, N);
    scan_bsum<<<1, 512>>>(p_bsum, p_boff, NB);
    scan_final<<<NB, CHUNK>>>(p_counts, p_boff, p_rowptr, p_cursor, N);
    fill_csr_kernel<<<gE, TB>>>(src, dst, p_cursor, p_colidx, E);

    // ---- conversions (xs = x * dinv), pool zero-init ----
    conv_x_kernel<<<(N * 40 + TB - 1) / TB, TB>>>(x, p_dinv, (__half2*)p_xs, N);
    conv_w_kernel<<<(128 * 96 + 128 * 128 + TB - 1) / TB, TB>>>(W0, W1, p_w0t, p_w1t);
    cudaMemsetAsync(p_pool, 0, (size_t)G * HD * sizeof(float));

    // ---- layer 0: aggregate-then-transform; GEMM stores h0*dinv ----
    agg0_kernel<<<gW, TB>>>((const uint2*)p_xs, p_rowptr, p_colidx, p_dinv, (uint2*)p_ax, N);
    gemm_h_kernel<<<N / 128, TB>>>(p_ax, p_w0t, b0, p_dinv, p_hh, 96);

    // ---- layer 1: agg + fused GEMM/max-pool (h1 never materialized) ----
    agg1_kernel<<<gW, TB>>>((const uint2*)p_hh, p_rowptr, p_colidx, p_dinv, (uint2*)p_ah, N);
    gemm_h_pool_kernel<<<N / 128, TB>>>(p_ah, p_w1t, b1, batch, p_pool, 128, G);

    // ---- FF head (fp32) ----
    {
        dim3 grid((G + 127) / 128, 2);
        gemm_ff_kernel<<<grid, TB>>>(p_pool, Wf0, bf0, p_ff, G, HD, 256);
    }
    {
        dim3 grid((G + 127) / 128, 1);
        gemm_ff_kernel<<<grid, TB>>>(p_ff, Wf1, bf1, out, G, 256, HD);
    }
}

// round 14
// speedup vs baseline: 1.0047x; 1.0047x over previous
#include <cuda_runtime.h>
#include <cuda_fp16.h>
#include <cstdint>

#define NMAX 400000
#define EMAX 1600000
#define GMAX 4096
#define HD   128
#define CHUNK 1024

#define APAD 40    // smem row stride in halves (32 data + 8 pad)

// -------- device scratch --------
__device__ int    g_counts [NMAX];
__device__ int    g_rowptr [NMAX + 1];
__device__ int    g_cursor [NMAX];
__device__ int    g_colidx [EMAX];
__device__ int    g_bsum   [512];
__device__ int    g_boff   [512];
__device__ float  g_dinv   [NMAX];
__device__ __half g_xs     [(size_t)NMAX * 80];    // x*dinv fp16, stride 80 (cols 78,79 = 0)
__device__ __half g_ax     [(size_t)NMAX * 96];    // layer-0 agg out, stride 96 (cols 78..95 = 0)
__device__ __half g_hh     [(size_t)NMAX * 128];   // h0*dinv after layer0 GEMM
__device__ __half g_ah     [(size_t)NMAX * 128];   // layer-1 agg out
__device__ __half g_w0t    [128 * 96];             // W0^T fp16 [n][k], k padded to 96
__device__ __half g_w1t    [128 * 128];            // W1^T fp16 [n][k]
__device__ float  g_pool   [(size_t)GMAX * HD];
__device__ float  g_ff     [(size_t)GMAX * 256];

// unpack uint2 (4 halves) and accumulate into float4
__device__ __forceinline__ void acc_u2(uint2 v, float4& a) {
    float2 f0 = __half22float2(*reinterpret_cast<__half2*>(&v.x));
    float2 f1 = __half22float2(*reinterpret_cast<__half2*>(&v.y));
    a.x += f0.x; a.y += f0.y; a.z += f1.x; a.w += f1.y;
}

__device__ __forceinline__ uint2 pack_f4(float4 a, float s) {
    uint2 o;
    __half2 h0 = __floats2half2_rn(a.x * s, a.y * s);
    __half2 h1 = __floats2half2_rn(a.z * s, a.w * s);
    o.x = *reinterpret_cast<uint32_t*>(&h0);
    o.y = *reinterpret_cast<uint32_t*>(&h1);
    return o;
}

// ---------------- degree / CSR build ----------------
__global__ void count_deg_kernel(const int* __restrict__ dst, int* counts, int E) {
    int e = blockIdx.x * blockDim.x + threadIdx.x;
    if (e < E) atomicAdd(&counts[dst[e]], 1);
}

__global__ void scan_chunk_sum(const int* __restrict__ counts, int* bsum,
                               float* __restrict__ dinv, int N) {
    __shared__ int sh[256];
    int base = blockIdx.x * CHUNK;
    int s = 0;
    for (int i = threadIdx.x; i < CHUNK; i += 256) {
        int g = base + i;
        int c = (g < N) ? counts[g] : 0;
        s += c;
        if (g < N) dinv[g] = rsqrtf((float)c + 1.0f);
    }
    sh[threadIdx.x] = s; __syncthreads();
    for (int o = 128; o > 0; o >>= 1) {
        if (threadIdx.x < o) sh[threadIdx.x] += sh[threadIdx.x + o];
        __syncthreads();
    }
    if (threadIdx.x == 0) bsum[blockIdx.x] = sh[0];
}

__global__ void scan_bsum(const int* __restrict__ bsum, int* boff, int NB) {
    __shared__ int sh[512];
    int v = (threadIdx.x < NB) ? bsum[threadIdx.x] : 0;
    sh[threadIdx.x] = v; __syncthreads();
    for (int o = 1; o < 512; o <<= 1) {
        int t = (threadIdx.x >= o) ? sh[threadIdx.x - o] : 0;
        __syncthreads();
        sh[threadIdx.x] += t;
        __syncthreads();
    }
    if (threadIdx.x < NB) boff[threadIdx.x] = sh[threadIdx.x] - v;  // exclusive
}

__global__ void scan_final(const int* __restrict__ counts, const int* __restrict__ boff,
                           int* rowptr, int* cursor, int N) {
    __shared__ int sh[CHUNK];
    int g = blockIdx.x * CHUNK + threadIdx.x;
    int v = (g < N) ? counts[g] : 0;
    sh[threadIdx.x] = v; __syncthreads();
    for (int o = 1; o < CHUNK; o <<= 1) {
        int t = (threadIdx.x >= o) ? sh[threadIdx.x - o] : 0;
        __syncthreads();
        sh[threadIdx.x] += t;
        __syncthreads();
    }
    if (g < N) {
        int excl = boff[blockIdx.x] + sh[threadIdx.x] - v;
        rowptr[g] = excl;
        cursor[g] = excl;
        if (g == N - 1) rowptr[N] = boff[blockIdx.x] + sh[threadIdx.x];
    }
}

__global__ void fill_csr_kernel(const int* __restrict__ src, const int* __restrict__ dst,
                                int* cursor, int* colidx, int E) {
    int e = blockIdx.x * blockDim.x + threadIdx.x;
    if (e < E) {
        int d = dst[e];
        int p = atomicAdd(&cursor[d], 1);
        colidx[p] = src[e];
    }
}

// ---------------- conversions ----------------
__global__ void conv_x_kernel(const float* __restrict__ x, const float* __restrict__ dinv,
                              __half2* __restrict__ xs2, int N) {
    int i = blockIdx.x * blockDim.x + threadIdx.x;   // over N*40 half2
    if (i >= N * 40) return;
    int n = i / 40;
    int c = i - n * 40;
    float dd = __ldg(&dinv[n]);
    float v0 = (2 * c     < 78) ? x[(size_t)n * 78 + 2 * c]     * dd : 0.0f;
    float v1 = (2 * c + 1 < 78) ? x[(size_t)n * 78 + 2 * c + 1] * dd : 0.0f;
    xs2[i] = __floats2half2_rn(v0, v1);
}

__global__ void conv_w_kernel(const float* __restrict__ W0, const float* __restrict__ W1,
                              __half* __restrict__ W0t, __half* __restrict__ W1t) {
    int i = blockIdx.x * blockDim.x + threadIdx.x;
    if (i < 128 * 96) {
        int n = i / 96;
        int k = i - n * 96;
        W0t[i] = (k < 78) ? __float2half_rn(W0[(size_t)k * 128 + n]) : __float2half_rn(0.0f);
    } else if (i < 128 * 96 + 128 * 128) {
        int j = i - 128 * 96;
        int n = j >> 7;
        int k = j & 127;
        W1t[j] = __float2half_rn(W1[(size_t)k * 128 + n]);
    }
}

// ---------------- agg0: ax[d] = h16( dinv[d]*(xs[d] + sum_{s} xs[s]) ), xs already *dinv ----------------
__global__ void agg0_kernel(const uint2* __restrict__ xsv, const int* __restrict__ rowptr,
                            const int* __restrict__ colidx, const float* __restrict__ dinv,
                            uint2* __restrict__ axv, int N)
{
    int w = (blockIdx.x * blockDim.x + threadIdx.x) >> 5;
    int lane = threadIdx.x & 31;
    if (w >= N) return;
    const bool act = lane < 20;

    float4 a = make_float4(0.f, 0.f, 0.f, 0.f);
    if (act) acc_u2(__ldg(&xsv[(size_t)w * 20 + lane]), a);

    int s0 = __ldg(&rowptr[w]);
    int s1 = __ldg(&rowptr[w + 1]);
    int e = s0;
    for (; e + 4 <= s1; e += 4) {
        int i0 = __ldg(&colidx[e + 0]);
        int i1 = __ldg(&colidx[e + 1]);
        int i2 = __ldg(&colidx[e + 2]);
        int i3 = __ldg(&colidx[e + 3]);
        if (act) {
            uint2 u0 = __ldg(&xsv[(size_t)i0 * 20 + lane]);
            uint2 u1 = __ldg(&xsv[(size_t)i1 * 20 + lane]);
            uint2 u2 = __ldg(&xsv[(size_t)i2 * 20 + lane]);
            uint2 u3 = __ldg(&xsv[(size_t)i3 * 20 + lane]);
            acc_u2(u0, a); acc_u2(u1, a); acc_u2(u2, a); acc_u2(u3, a);
        }
    }
    for (; e < s1; e++) {
        int s = __ldg(&colidx[e]);
        if (act) acc_u2(__ldg(&xsv[(size_t)s * 20 + lane]), a);
    }

    float dd = __ldg(&dinv[w]);
    if (act)
        axv[(size_t)w * 24 + lane] = pack_f4(a, dd);
    else if (lane < 24)
        axv[(size_t)w * 24 + lane] = make_uint2(0u, 0u);   // pad halves 80..95
}

// ---------------- agg1 (128-dim): ah[d] = h16( dinv[d]*(hs[d] + sum_{s} hs[s]) ), hs = h0*dinv ----------------
__global__ void agg1_kernel(const uint2* __restrict__ hsv, const int* __restrict__ rowptr,
                            const int* __restrict__ colidx, const float* __restrict__ dinv,
                            uint2* __restrict__ ahv, int N)
{
    int w = (blockIdx.x * blockDim.x + threadIdx.x) >> 5;
    int lane = threadIdx.x & 31;
    if (w >= N) return;

    float4 a = make_float4(0.f, 0.f, 0.f, 0.f);
    acc_u2(__ldg(&hsv[(size_t)w * 32 + lane]), a);

    int s0 = __ldg(&rowptr[w]);
    int s1 = __ldg(&rowptr[w + 1]);
    int e = s0;
    for (; e + 4 <= s1; e += 4) {
        int i0 = __ldg(&colidx[e + 0]);
        int i1 = __ldg(&colidx[e + 1]);
        int i2 = __ldg(&colidx[e + 2]);
        int i3 = __ldg(&colidx[e + 3]);
        uint2 u0 = __ldg(&hsv[(size_t)i0 * 32 + lane]);
        uint2 u1 = __ldg(&hsv[(size_t)i1 * 32 + lane]);
        uint2 u2 = __ldg(&hsv[(size_t)i2 * 32 + lane]);
        uint2 u3 = __ldg(&hsv[(size_t)i3 * 32 + lane]);
        acc_u2(u0, a); acc_u2(u1, a); acc_u2(u2, a); acc_u2(u3, a);
    }
    for (; e < s1; e++) {
        int s = __ldg(&colidx[e]);
        acc_u2(__ldg(&hsv[(size_t)s * 32 + lane]), a);
    }

    float dd = __ldg(&dinv[w]);
    ahv[(size_t)w * 32 + lane] = pack_f4(a, dd);
}

// ---------------- fp16 tensor-core GEMM (layer 0): hh = h16(relu(A@Wt^T + bias) * rowscale) ----------------
__global__ void __launch_bounds__(256, 2)
gemm_h_kernel(const __half* __restrict__ A, const __half* __restrict__ Wt,
              const float* __restrict__ bias, const float* __restrict__ rowscale,
              __half* __restrict__ out, int K)
{
    __shared__ __half As[2][128 * APAD];
    __shared__ __half Bs[2][128 * APAD];

    const int tid  = threadIdx.x;
    const int row0 = blockIdx.x * 128;
    const int lane = tid & 31;
    const int wid  = tid >> 5;
    const int gid  = lane >> 2;
    const int tig  = lane & 3;
    const int wm   = (wid & 1) * 64;
    const int wn   = (wid >> 1) * 32;

    float c[4][4][4];
#pragma unroll
    for (int i = 0; i < 4; i++)
#pragma unroll
        for (int j = 0; j < 4; j++)
#pragma unroll
            for (int r = 0; r < 4; r++) c[i][j][r] = 0.0f;

    const int KC = K >> 5;

    auto issue = [&](int kc, int buf) {
        const int k0 = kc << 5;
#pragma unroll
        for (int rpt = 0; rpt < 2; rpt++) {
            int i = tid + rpt * 256;
            int m = i >> 2, ch = i & 3;
            const __half* src = A + (size_t)(row0 + m) * K + k0 + ch * 8;
            uint32_t dst = (uint32_t)__cvta_generic_to_shared(&As[buf][m * APAD + ch * 8]);
            asm volatile("cp.async.cg.shared.global [%0], [%1], 16;" :: "r"(dst), "l"(src));
        }
#pragma unroll
        for (int rpt = 0; rpt < 2; rpt++) {
            int i = tid + rpt * 256;
            int n = i >> 2, ch = i & 3;
            const __half* src = Wt + (size_t)n * K + k0 + ch * 8;
            uint32_t dst = (uint32_t)__cvta_generic_to_shared(&Bs[buf][n * APAD + ch * 8]);
            asm volatile("cp.async.cg.shared.global [%0], [%1], 16;" :: "r"(dst), "l"(src));
        }
        asm volatile("cp.async.commit_group;" ::: "memory");
    };

    issue(0, 0);

    for (int kc = 0; kc < KC; kc++) {
        const int buf = kc & 1;
        asm volatile("cp.async.wait_group 0;" ::: "memory");
        __syncthreads();
        if (kc + 1 < KC) issue(kc + 1, buf ^ 1);

#pragma unroll
        for (int s = 0; s < 2; s++) {
            const int ks = s * 16;
            uint32_t a[4][4];
#pragma unroll
            for (int mf = 0; mf < 4; mf++) {
                const __half* ab = &As[buf][(wm + mf * 16 + gid) * APAD + ks];
                a[mf][0] = *reinterpret_cast<const uint32_t*>(&ab[2 * tig]);
                a[mf][1] = *reinterpret_cast<const uint32_t*>(&ab[8 * APAD + 2 * tig]);
                a[mf][2] = *reinterpret_cast<const uint32_t*>(&ab[2 * tig + 8]);
                a[mf][3] = *reinterpret_cast<const uint32_t*>(&ab[8 * APAD + 2 * tig + 8]);
            }
            uint32_t b[4][2];
#pragma unroll
            for (int nf = 0; nf < 4; nf++) {
                const __half* bb = &Bs[buf][(wn + nf * 8 + gid) * APAD + ks];
                b[nf][0] = *reinterpret_cast<const uint32_t*>(&bb[2 * tig]);
                b[nf][1] = *reinterpret_cast<const uint32_t*>(&bb[2 * tig + 8]);
            }
#pragma unroll
            for (int mf = 0; mf < 4; mf++)
#pragma unroll
                for (int nf = 0; nf < 4; nf++) {
                    asm volatile(
                        "mma.sync.aligned.m16n8k16.row.col.f32.f16.f16.f32 "
                        "{%0,%1,%2,%3}, {%4,%5,%6,%7}, {%8,%9}, {%0,%1,%2,%3};"
                        : "+f"(c[mf][nf][0]), "+f"(c[mf][nf][1]),
                          "+f"(c[mf][nf][2]), "+f"(c[mf][nf][3])
                        : "r"(a[mf][0]), "r"(a[mf][1]), "r"(a[mf][2]), "r"(a[mf][3]),
                          "r"(b[nf][0]), "r"(b[nf][1]));
                }
        }
        __syncthreads();
    }

    float bxv[4], byv[4];
#pragma unroll
    for (int nf = 0; nf < 4; nf++) {
        const int cc = wn + nf * 8 + 2 * tig;
        bxv[nf] = bias[cc];
        byv[nf] = bias[cc + 1];
    }
#pragma unroll
    for (int mf = 0; mf < 4; mf++) {
        const int r0 = row0 + wm + mf * 16 + gid;
        float rs0 = rowscale[r0], rs1 = rowscale[r0 + 8];
#pragma unroll
        for (int nf = 0; nf < 4; nf++) {
            const int cc = wn + nf * 8 + 2 * tig;
            __half2 v0 = __floats2half2_rn(fmaxf(c[mf][nf][0] + bxv[nf], 0.f) * rs0,
                                           fmaxf(c[mf][nf][1] + byv[nf], 0.f) * rs0);
            __half2 v1 = __floats2half2_rn(fmaxf(c[mf][nf][2] + bxv[nf], 0.f) * rs1,
                                           fmaxf(c[mf][nf][3] + byv[nf], 0.f) * rs1);
            *reinterpret_cast<__half2*>(&out[(size_t)r0 * 128 + cc]) = v0;
            *reinterpret_cast<__half2*>(&out[(size_t)(r0 + 8) * 128 + cc]) = v1;
        }
    }
}

// ---------------- fused layer-1 GEMM + global max pool ----------------
__global__ void __launch_bounds__(256, 2)
gemm_h_pool_kernel(const __half* __restrict__ A, const __half* __restrict__ Wt,
                   const float* __restrict__ bias, const int* __restrict__ batch,
                   float* __restrict__ pool, int K, int G)
{
    __shared__ __half As[2][128 * APAD];
    __shared__ __half Bs[2][128 * APAD];
    __shared__ unsigned int pool_s[4 * 128];   // up to 4 graph segments per 128-row block

    const int tid  = threadIdx.x;
    const int row0 = blockIdx.x * 128;
    const int lane = tid & 31;
    const int wid  = tid >> 5;
    const int gid  = lane >> 2;
    const int tig  = lane & 3;
    const int wm   = (wid & 1) * 64;
    const int wn   = (wid >> 1) * 32;

    for (int i = tid; i < 4 * 128; i += 256) pool_s[i] = 0u;

    float c[4][4][4];
#pragma unroll
    for (int i = 0; i < 4; i++)
#pragma unroll
        for (int j = 0; j < 4; j++)
#pragma unroll
            for (int r = 0; r < 4; r++) c[i][j][r] = 0.0f;

    const int KC = K >> 5;

    auto issue = [&](int kc, int buf) {
        const int k0 = kc << 5;
#pragma unroll
        for (int rpt = 0; rpt < 2; rpt++) {
            int i = tid + rpt * 256;
            int m = i >> 2, ch = i & 3;
            const __half* src = A + (size_t)(row0 + m) * K + k0 + ch * 8;
            uint32_t dst = (uint32_t)__cvta_generic_to_shared(&As[buf][m * APAD + ch * 8]);
            asm volatile("cp.async.cg.shared.global [%0], [%1], 16;" :: "r"(dst), "l"(src));
        }
#pragma unroll
        for (int rpt = 0; rpt < 2; rpt++) {
            int i = tid + rpt * 256;
            int n = i >> 2, ch = i & 3;
            const __half* src = Wt + (size_t)n * K + k0 + ch * 8;
            uint32_t dst = (uint32_t)__cvta_generic_to_shared(&Bs[buf][n * APAD + ch * 8]);
            asm volatile("cp.async.cg.shared.global [%0], [%1], 16;" :: "r"(dst), "l"(src));
        }
        asm volatile("cp.async.commit_group;" ::: "memory");
    };

    issue(0, 0);

    for (int kc = 0; kc < KC; kc++) {
        const int buf = kc & 1;
        asm volatile("cp.async.wait_group 0;" ::: "memory");
        __syncthreads();
        if (kc + 1 < KC) issue(kc + 1, buf ^ 1);

#pragma unroll
        for (int s = 0; s < 2; s++) {
            const int ks = s * 16;
            uint32_t a[4][4];
#pragma unroll
            for (int mf = 0; mf < 4; mf++) {
                const __half* ab = &As[buf][(wm + mf * 16 + gid) * APAD + ks];
                a[mf][0] = *reinterpret_cast<const uint32_t*>(&ab[2 * tig]);
                a[mf][1] = *reinterpret_cast<const uint32_t*>(&ab[8 * APAD + 2 * tig]);
                a[mf][2] = *reinterpret_cast<const uint32_t*>(&ab[2 * tig + 8]);
                a[mf][3] = *reinterpret_cast<const uint32_t*>(&ab[8 * APAD + 2 * tig + 8]);
            }
            uint32_t b[4][2];
#pragma unroll
            for (int nf = 0; nf < 4; nf++) {
                const __half* bb = &Bs[buf][(wn + nf * 8 + gid) * APAD + ks];
                b[nf][0] = *reinterpret_cast<const uint32_t*>(&bb[2 * tig]);
                b[nf][1] = *reinterpret_cast<const uint32_t*>(&bb[2 * tig + 8]);
            }
#pragma unroll
            for (int mf = 0; mf < 4; mf++)
#pragma unroll
                for (int nf = 0; nf < 4; nf++) {
                    asm volatile(
                        "mma.sync.aligned.m16n8k16.row.col.f32.f16.f16.f32 "
                        "{%0,%1,%2,%3}, {%4,%5,%6,%7}, {%8,%9}, {%0,%1,%2,%3};"
                        : "+f"(c[mf][nf][0]), "+f"(c[mf][nf][1]),
                          "+f"(c[mf][nf][2]), "+f"(c[mf][nf][3])
                        : "r"(a[mf][0]), "r"(a[mf][1]), "r"(a[mf][2]), "r"(a[mf][3]),
                          "r"(b[nf][0]), "r"(b[nf][1]));
                }
        }
        __syncthreads();
    }

    // epilogue: relu(acc+bias) -> per-segment smem max -> global atomicMax
    float bxv[4], byv[4];
#pragma unroll
    for (int nf = 0; nf < 4; nf++) {
        const int cc = wn + nf * 8 + 2 * tig;
        bxv[nf] = bias[cc];
        byv[nf] = bias[cc + 1];
    }
    const int gbase = __ldg(&batch[row0]);
#pragma unroll
    for (int mf = 0; mf < 4; mf++) {
        const int r0 = row0 + wm + mf * 16 + gid;
        const int seg0 = __ldg(&batch[r0]) - gbase;
        const int seg1 = __ldg(&batch[r0 + 8]) - gbase;
#pragma unroll
        for (int nf = 0; nf < 4; nf++) {
            const int cc = wn + nf * 8 + 2 * tig;
            float v00 = fmaxf(c[mf][nf][0] + bxv[nf], 0.f);
            float v01 = fmaxf(c[mf][nf][1] + byv[nf], 0.f);
            float v10 = fmaxf(c[mf][nf][2] + bxv[nf], 0.f);
            float v11 = fmaxf(c[mf][nf][3] + byv[nf], 0.f);
            atomicMax(&pool_s[seg0 * 128 + cc],     __float_as_uint(v00));
            atomicMax(&pool_s[seg0 * 128 + cc + 1], __float_as_uint(v01));
            atomicMax(&pool_s[seg1 * 128 + cc],     __float_as_uint(v10));
            atomicMax(&pool_s[seg1 * 128 + cc + 1], __float_as_uint(v11));
        }
    }
    __syncthreads();
    for (int i = tid; i < 4 * 128; i += 256) {
        int g = gbase + (i >> 7);
        unsigned int v = pool_s[i];
        if (g < G && v != 0u)
            atomicMax(reinterpret_cast<unsigned int*>(&pool[(size_t)g * 128 + (i & 127)]), v);
    }
}

// ---------------- FFMA GEMM for FF head (full fp32): out = relu(A@W + bias) ----------------
__global__ void __launch_bounds__(256, 2)
gemm_ff_kernel(const float* __restrict__ A, const float* __restrict__ W,
               const float* __restrict__ bias, float* __restrict__ out,
               int M, int K, int Nout)
{
    __shared__ float As[16 * 128];
    __shared__ float Bs[16 * 128];

    const int tid  = threadIdx.x;
    const int tx   = tid & 15;
    const int ty   = tid >> 4;
    const int row0 = blockIdx.x * 128;
    const int col0 = blockIdx.y * 128;

    float acc[8][8];
#pragma unroll
    for (int i = 0; i < 8; i++)
#pragma unroll
        for (int j = 0; j < 8; j++) acc[i][j] = 0.0f;

    const int KC = (K + 15) >> 4;
    for (int kc = 0; kc < KC; kc++) {
        const int k0 = kc << 4;
        for (int i = tid; i < 512; i += 256) {
            int m = i >> 2, kv = (i & 3) << 2;
            int row = row0 + m;
            float4 v = make_float4(0.f, 0.f, 0.f, 0.f);
            if (row < M && (k0 + kv) < K)
                v = *reinterpret_cast<const float4*>(&A[(size_t)row * K + k0 + kv]);
            As[(kv + 0) * 128 + m] = v.x;
            As[(kv + 1) * 128 + m] = v.y;
            As[(kv + 2) * 128 + m] = v.z;
            As[(kv + 3) * 128 + m] = v.w;
        }
        for (int i = tid; i < 512; i += 256) {
            int kk = i >> 5, n4 = (i & 31) << 2;
            float4 v = make_float4(0.f, 0.f, 0.f, 0.f);
            if ((k0 + kk) < K)
                v = *reinterpret_cast<const float4*>(&W[(size_t)(k0 + kk) * Nout + col0 + n4]);
            *reinterpret_cast<float4*>(&Bs[kk * 128 + n4]) = v;
        }
        __syncthreads();
#pragma unroll
        for (int kk = 0; kk < 16; kk++) {
            float4 a0 = *reinterpret_cast<const float4*>(&As[kk * 128 + ty * 8]);
            float4 a1 = *reinterpret_cast<const float4*>(&As[kk * 128 + ty * 8 + 4]);
            float4 b0 = *reinterpret_cast<const float4*>(&Bs[kk * 128 + tx * 8]);
            float4 b1 = *reinterpret_cast<const float4*>(&Bs[kk * 128 + tx * 8 + 4]);
            float av[8] = {a0.x, a0.y, a0.z, a0.w, a1.x, a1.y, a1.z, a1.w};
            float bv[8] = {b0.x, b0.y, b0.z, b0.w, b1.x, b1.y, b1.z, b1.w};
#pragma unroll
            for (int i = 0; i < 8; i++)
#pragma unroll
                for (int j = 0; j < 8; j++)
                    acc[i][j] += av[i] * bv[j];
        }
        __syncthreads();
    }

#pragma unroll
    for (int i = 0; i < 8; i++) {
        int row = row0 + ty * 8 + i;
        if (row >= M) break;
        const float4 b0 = *reinterpret_cast<const float4*>(&bias[col0 + tx * 8]);
        const float4 b1 = *reinterpret_cast<const float4*>(&bias[col0 + tx * 8 + 4]);
        float4 v0 = make_float4(fmaxf(acc[i][0] + b0.x, 0.f), fmaxf(acc[i][1] + b0.y, 0.f),
                                fmaxf(acc[i][2] + b0.z, 0.f), fmaxf(acc[i][3] + b0.w, 0.f));
        float4 v1 = make_float4(fmaxf(acc[i][4] + b1.x, 0.f), fmaxf(acc[i][5] + b1.y, 0.f),
                                fmaxf(acc[i][6] + b1.z, 0.f), fmaxf(acc[i][7] + b1.w, 0.f));
        float4* o = reinterpret_cast<float4*>(&out[(size_t)row * Nout + col0 + tx * 8]);
        o[0] = v0; o[1] = v1;
    }
}

// ---------------- launch ----------------
extern "C" void kernel_launch(void* const* d_in, const int* in_sizes, int n_in,
                              void* d_out, int out_size)
{
    const float* x     = (const float*)d_in[0];
    const int*   ei    = (const int*)d_in[1];
    const int*   batch = (const int*)d_in[2];
    const float* W0    = (const float*)d_in[3];
    const float* b0    = (const float*)d_in[4];
    const float* W1    = (const float*)d_in[5];
    const float* b1    = (const float*)d_in[6];
    const float* Wf0   = (const float*)d_in[7];
    const float* bf0   = (const float*)d_in[8];
    const float* Wf1   = (const float*)d_in[9];
    const float* bf1   = (const float*)d_in[10];
    float*       out   = (float*)d_out;

    const int F_IN = 78;
    const int N = in_sizes[0] / F_IN;
    const int E = in_sizes[1] / 2;
    const int G = out_size / HD;

    const int* src = ei;
    const int* dst = ei + E;

    int *p_counts, *p_rowptr, *p_cursor, *p_colidx, *p_bsum, *p_boff;
    float *p_dinv, *p_pool, *p_ff;
    __half *p_xs, *p_ax, *p_hh, *p_ah, *p_w0t, *p_w1t;
    cudaGetSymbolAddress((void**)&p_counts, g_counts);
    cudaGetSymbolAddress((void**)&p_rowptr, g_rowptr);
    cudaGetSymbolAddress((void**)&p_cursor, g_cursor);
    cudaGetSymbolAddress((void**)&p_colidx, g_colidx);
    cudaGetSymbolAddress((void**)&p_bsum,   g_bsum);
    cudaGetSymbolAddress((void**)&p_boff,   g_boff);
    cudaGetSymbolAddress((void**)&p_dinv,   g_dinv);
    cudaGetSymbolAddress((void**)&p_xs,     g_xs);
    cudaGetSymbolAddress((void**)&p_ax,     g_ax);
    cudaGetSymbolAddress((void**)&p_hh,     g_hh);
    cudaGetSymbolAddress((void**)&p_ah,     g_ah);
    cudaGetSymbolAddress((void**)&p_w0t,    g_w0t);
    cudaGetSymbolAddress((void**)&p_w1t,    g_w1t);
    cudaGetSymbolAddress((void**)&p_pool,   g_pool);
    cudaGetSymbolAddress((void**)&p_ff,     g_ff);

    // side stream + events (created once on the uncaptured correctness call)
    static cudaStream_t s2 = nullptr;
    static cudaEvent_t ev_entry = nullptr, ev_dinv = nullptr, ev_conv = nullptr;
    if (!s2) {
        cudaStreamCreateWithFlags(&s2, cudaStreamNonBlocking);
        cudaEventCreateWithFlags(&ev_entry, cudaEventDisableTiming);
        cudaEventCreateWithFlags(&ev_dinv,  cudaEventDisableTiming);
        cudaEventCreateWithFlags(&ev_conv,  cudaEventDisableTiming);
    }

    const int TB = 256;
    int gE = (E + TB - 1) / TB;
    int NB = (N + CHUNK - 1) / CHUNK;
    int gW = (N * 32 + TB - 1) / TB;   // warp-per-node grids

    // ---- fork: side stream does weight conversion + pool zero-init ----
    cudaEventRecord(ev_entry, 0);
    cudaStreamWaitEvent(s2, ev_entry, 0);
    conv_w_kernel<<<(128 * 96 + 128 * 128 + TB - 1) / TB, TB, 0, s2>>>(W0, W1, p_w0t, p_w1t);
    cudaMemsetAsync(p_pool, 0, (size_t)G * HD * sizeof(float), s2);

    // ---- main stream: CSR build + norm ----
    cudaMemsetAsync(p_counts, 0, (size_t)N * sizeof(int));
    count_deg_kernel<<<gE, TB>>>(dst, p_counts, E);
    scan_chunk_sum<<<NB, 256>>>(p_counts, p_bsum, p_dinv, N);
    cudaEventRecord(ev_dinv, 0);              // dinv ready -> conv_x can start on s2
    cudaStreamWaitEvent(s2, ev_dinv, 0);
    conv_x_kernel<<<(N * 40 + TB - 1) / TB, TB, 0, s2>>>(x, p_dinv, (__half2*)p_xs, N);
    cudaEventRecord(ev_conv, s2);

    scan_bsum<<<1, 512>>>(p_bsum, p_boff, NB);
    scan_final<<<NB, CHUNK>>>(p_counts, p_boff, p_rowptr, p_cursor, N);
    fill_csr_kernel<<<gE, TB>>>(src, dst, p_cursor, p_colidx, E);

    // ---- join: agg0 needs xs (s2) + CSR (main); gemm needs w0t (s2) ----
    cudaStreamWaitEvent(0, ev_conv, 0);

    // ---- layer 0: aggregate-then-transform; GEMM stores h0*dinv ----
    agg0_kernel<<<gW, TB>>>((const uint2*)p_xs, p_rowptr, p_colidx, p_dinv, (uint2*)p_ax, N);
    gemm_h_kernel<<<N / 128, TB>>>(p_ax, p_w0t, b0, p_dinv, p_hh, 96);

    // ---- layer 1: agg + fused GEMM/max-pool (h1 never materialized) ----
    agg1_kernel<<<gW, TB>>>((const uint2*)p_hh, p_rowptr, p_colidx, p_dinv, (uint2*)p_ah, N);
    gemm_h_pool_kernel<<<N / 128, TB>>>(p_ah, p_w1t, b1, batch, p_pool, 128, G);

    // ---- FF head (fp32) ----
    {
        dim3 grid((G + 127) / 128, 2);
        gemm_ff_kernel<<<grid, TB>>>(p_pool, Wf0, bf0, p_ff, G, HD, 256);
    }
    {
        dim3 grid((G + 127) / 128, 1);
        gemm_ff_kernel<<<grid, TB>>>(p_ff, Wf1, bf1, out, G, 256, HD);
    }
}

// round 15
// speedup vs baseline: 1.0233x; 1.0185x over previous
#include <cuda_runtime.h>
#include <cuda_fp16.h>
#include <cstdint>

#define NMAX 400000
#define EMAX 1600000
#define GMAX 4096
#define HD   128
#define CHUNK 1024

#define APAD 40    // smem row stride in halves (32 data + 8 pad)

// -------- device scratch --------
__device__ int    g_counts [NMAX];
__device__ int    g_rowptr [NMAX + 1];
__device__ int    g_cursor [NMAX];
__device__ int    g_colidx [EMAX];
__device__ int    g_bsum   [512];
__device__ int    g_boff   [512];
__device__ float  g_dinv   [NMAX];
__device__ __half g_xs     [(size_t)NMAX * 80];    // x*dinv fp16, stride 80 (cols 78,79 = 0)
__device__ __half g_ax     [(size_t)NMAX * 96];    // layer-0 agg out, stride 96 (cols 78..95 = 0)
__device__ __half g_hh     [(size_t)NMAX * 128];   // h0*dinv after layer0 GEMM
__device__ __half g_ah     [(size_t)NMAX * 128];   // layer-1 agg out
__device__ __half g_w0t    [128 * 96];             // W0^T fp16 [n][k], k padded to 96
__device__ __half g_w1t    [128 * 128];            // W1^T fp16 [n][k]
__device__ float  g_pool   [(size_t)GMAX * HD];
__device__ float  g_ff     [(size_t)GMAX * 256];

// unpack uint2 (4 halves) and accumulate into float4
__device__ __forceinline__ void acc_u2(uint2 v, float4& a) {
    float2 f0 = __half22float2(*reinterpret_cast<__half2*>(&v.x));
    float2 f1 = __half22float2(*reinterpret_cast<__half2*>(&v.y));
    a.x += f0.x; a.y += f0.y; a.z += f1.x; a.w += f1.y;
}

__device__ __forceinline__ uint2 pack_f4(float4 a, float s) {
    uint2 o;
    __half2 h0 = __floats2half2_rn(a.x * s, a.y * s);
    __half2 h1 = __floats2half2_rn(a.z * s, a.w * s);
    o.x = *reinterpret_cast<uint32_t*>(&h0);
    o.y = *reinterpret_cast<uint32_t*>(&h1);
    return o;
}

// ---------------- degree / CSR build ----------------
__global__ void count_deg_kernel(const int* __restrict__ dst, int* counts, int E) {
    int e = blockIdx.x * blockDim.x + threadIdx.x;
    if (e < E) atomicAdd(&counts[dst[e]], 1);
}

__global__ void scan_chunk_sum(const int* __restrict__ counts, int* bsum,
                               float* __restrict__ dinv, int N) {
    __shared__ int sh[256];
    int base = blockIdx.x * CHUNK;
    int s = 0;
    for (int i = threadIdx.x; i < CHUNK; i += 256) {
        int g = base + i;
        int c = (g < N) ? counts[g] : 0;
        s += c;
        if (g < N) dinv[g] = rsqrtf((float)c + 1.0f);
    }
    sh[threadIdx.x] = s; __syncthreads();
    for (int o = 128; o > 0; o >>= 1) {
        if (threadIdx.x < o) sh[threadIdx.x] += sh[threadIdx.x + o];
        __syncthreads();
    }
    if (threadIdx.x == 0) bsum[blockIdx.x] = sh[0];
}

__global__ void scan_bsum(const int* __restrict__ bsum, int* boff, int NB) {
    __shared__ int sh[512];
    int v = (threadIdx.x < NB) ? bsum[threadIdx.x] : 0;
    sh[threadIdx.x] = v; __syncthreads();
    for (int o = 1; o < 512; o <<= 1) {
        int t = (threadIdx.x >= o) ? sh[threadIdx.x - o] : 0;
        __syncthreads();
        sh[threadIdx.x] += t;
        __syncthreads();
    }
    if (threadIdx.x < NB) boff[threadIdx.x] = sh[threadIdx.x] - v;  // exclusive
}

__global__ void scan_final(const int* __restrict__ counts, const int* __restrict__ boff,
                           int* rowptr, int* cursor, int N) {
    __shared__ int sh[CHUNK];
    int g = blockIdx.x * CHUNK + threadIdx.x;
    int v = (g < N) ? counts[g] : 0;
    sh[threadIdx.x] = v; __syncthreads();
    for (int o = 1; o < CHUNK; o <<= 1) {
        int t = (threadIdx.x >= o) ? sh[threadIdx.x - o] : 0;
        __syncthreads();
        sh[threadIdx.x] += t;
        __syncthreads();
    }
    if (g < N) {
        int excl = boff[blockIdx.x] + sh[threadIdx.x] - v;
        rowptr[g] = excl;
        cursor[g] = excl;
        if (g == N - 1) rowptr[N] = boff[blockIdx.x] + sh[threadIdx.x];
    }
}

__global__ void fill_csr_kernel(const int* __restrict__ src, const int* __restrict__ dst,
                                int* cursor, int* colidx, int E) {
    int e = blockIdx.x * blockDim.x + threadIdx.x;
    if (e < E) {
        int d = dst[e];
        int p = atomicAdd(&cursor[d], 1);
        colidx[p] = src[e];
    }
}

// ---------------- conversions ----------------
// flat float2 pass: i covers half2-column c of node n (exact coverage, no predicates)
__global__ void conv_x_kernel(const float2* __restrict__ x2, const float* __restrict__ dinv,
                              __half2* __restrict__ xs2, int N) {
    int i = blockIdx.x * blockDim.x + threadIdx.x;   // over N*39 float2
    if (i >= N * 39) return;
    int n = i / 39;
    int c = i - n * 39;
    float dd = __ldg(&dinv[n]);
    float2 v = __ldg(&x2[i]);                         // == x[n*78 + 2c .. +1]
    xs2[n * 40 + c] = __floats2half2_rn(v.x * dd, v.y * dd);
    if (c == 38) xs2[n * 40 + 39] = __floats2half2_rn(0.f, 0.f);   // pad cols 78,79
}

__global__ void conv_w_kernel(const float* __restrict__ W0, const float* __restrict__ W1,
                              __half* __restrict__ W0t, __half* __restrict__ W1t) {
    int i = blockIdx.x * blockDim.x + threadIdx.x;
    if (i < 128 * 96) {
        int n = i / 96;
        int k = i - n * 96;
        W0t[i] = (k < 78) ? __float2half_rn(W0[(size_t)k * 128 + n]) : __float2half_rn(0.0f);
    } else if (i < 128 * 96 + 128 * 128) {
        int j = i - 128 * 96;
        int n = j >> 7;
        int k = j & 127;
        W1t[j] = __float2half_rn(W1[(size_t)k * 128 + n]);
    }
}

// ---------------- agg0: ax[d] = h16( dinv[d]*(xs[d] + sum_{s} xs[s]) ), xs already *dinv ----------------
__global__ void agg0_kernel(const uint2* __restrict__ xsv, const int* __restrict__ rowptr,
                            const int* __restrict__ colidx, const float* __restrict__ dinv,
                            uint2* __restrict__ axv, int N)
{
    int w = (blockIdx.x * blockDim.x + threadIdx.x) >> 5;
    int lane = threadIdx.x & 31;
    if (w >= N) return;
    const bool act = lane < 20;

    float4 a = make_float4(0.f, 0.f, 0.f, 0.f);
    if (act) acc_u2(__ldg(&xsv[(size_t)w * 20 + lane]), a);

    int s0 = __ldg(&rowptr[w]);
    int s1 = __ldg(&rowptr[w + 1]);
    int e = s0;
    for (; e + 4 <= s1; e += 4) {
        int i0 = __ldg(&colidx[e + 0]);
        int i1 = __ldg(&colidx[e + 1]);
        int i2 = __ldg(&colidx[e + 2]);
        int i3 = __ldg(&colidx[e + 3]);
        if (act) {
            uint2 u0 = __ldg(&xsv[(size_t)i0 * 20 + lane]);
            uint2 u1 = __ldg(&xsv[(size_t)i1 * 20 + lane]);
            uint2 u2 = __ldg(&xsv[(size_t)i2 * 20 + lane]);
            uint2 u3 = __ldg(&xsv[(size_t)i3 * 20 + lane]);
            acc_u2(u0, a); acc_u2(u1, a); acc_u2(u2, a); acc_u2(u3, a);
        }
    }
    for (; e < s1; e++) {
        int s = __ldg(&colidx[e]);
        if (act) acc_u2(__ldg(&xsv[(size_t)s * 20 + lane]), a);
    }

    float dd = __ldg(&dinv[w]);
    if (act)
        axv[(size_t)w * 24 + lane] = pack_f4(a, dd);
    else if (lane < 24)
        axv[(size_t)w * 24 + lane] = make_uint2(0u, 0u);   // pad halves 80..95
}

// ---------------- agg1 (128-dim): ah[d] = h16( dinv[d]*(hs[d] + sum_{s} hs[s]) ), hs = h0*dinv ----------------
__global__ void agg1_kernel(const uint2* __restrict__ hsv, const int* __restrict__ rowptr,
                            const int* __restrict__ colidx, const float* __restrict__ dinv,
                            uint2* __restrict__ ahv, int N)
{
    int w = (blockIdx.x * blockDim.x + threadIdx.x) >> 5;
    int lane = threadIdx.x & 31;
    if (w >= N) return;

    float4 a = make_float4(0.f, 0.f, 0.f, 0.f);
    acc_u2(__ldg(&hsv[(size_t)w * 32 + lane]), a);

    int s0 = __ldg(&rowptr[w]);
    int s1 = __ldg(&rowptr[w + 1]);
    int e = s0;
    for (; e + 4 <= s1; e += 4) {
        int i0 = __ldg(&colidx[e + 0]);
        int i1 = __ldg(&colidx[e + 1]);
        int i2 = __ldg(&colidx[e + 2]);
        int i3 = __ldg(&colidx[e + 3]);
        uint2 u0 = __ldg(&hsv[(size_t)i0 * 32 + lane]);
        uint2 u1 = __ldg(&hsv[(size_t)i1 * 32 + lane]);
        uint2 u2 = __ldg(&hsv[(size_t)i2 * 32 + lane]);
        uint2 u3 = __ldg(&hsv[(size_t)i3 * 32 + lane]);
        acc_u2(u0, a); acc_u2(u1, a); acc_u2(u2, a); acc_u2(u3, a);
    }
    for (; e < s1; e++) {
        int s = __ldg(&colidx[e]);
        acc_u2(__ldg(&hsv[(size_t)s * 32 + lane]), a);
    }

    float dd = __ldg(&dinv[w]);
    ahv[(size_t)w * 32 + lane] = pack_f4(a, dd);
}

// ---------------- fp16 tensor-core GEMM (layer 0): hh = h16(relu(A@Wt^T + bias) * rowscale) ----------------
__global__ void __launch_bounds__(256, 2)
gemm_h_kernel(const __half* __restrict__ A, const __half* __restrict__ Wt,
              const float* __restrict__ bias, const float* __restrict__ rowscale,
              __half* __restrict__ out, int K)
{
    __shared__ __half As[2][128 * APAD];
    __shared__ __half Bs[2][128 * APAD];

    const int tid  = threadIdx.x;
    const int row0 = blockIdx.x * 128;
    const int lane = tid & 31;
    const int wid  = tid >> 5;
    const int gid  = lane >> 2;
    const int tig  = lane & 3;
    const int wm   = (wid & 1) * 64;
    const int wn   = (wid >> 1) * 32;

    float c[4][4][4];
#pragma unroll
    for (int i = 0; i < 4; i++)
#pragma unroll
        for (int j = 0; j < 4; j++)
#pragma unroll
            for (int r = 0; r < 4; r++) c[i][j][r] = 0.0f;

    const int KC = K >> 5;

    auto issue = [&](int kc, int buf) {
        const int k0 = kc << 5;
#pragma unroll
        for (int rpt = 0; rpt < 2; rpt++) {
            int i = tid + rpt * 256;
            int m = i >> 2, ch = i & 3;
            const __half* src = A + (size_t)(row0 + m) * K + k0 + ch * 8;
            uint32_t dst = (uint32_t)__cvta_generic_to_shared(&As[buf][m * APAD + ch * 8]);
            asm volatile("cp.async.cg.shared.global [%0], [%1], 16;" :: "r"(dst), "l"(src));
        }
#pragma unroll
        for (int rpt = 0; rpt < 2; rpt++) {
            int i = tid + rpt * 256;
            int n = i >> 2, ch = i & 3;
            const __half* src = Wt + (size_t)n * K + k0 + ch * 8;
            uint32_t dst = (uint32_t)__cvta_generic_to_shared(&Bs[buf][n * APAD + ch * 8]);
            asm volatile("cp.async.cg.shared.global [%0], [%1], 16;" :: "r"(dst), "l"(src));
        }
        asm volatile("cp.async.commit_group;" ::: "memory");
    };

    issue(0, 0);

    for (int kc = 0; kc < KC; kc++) {
        const int buf = kc & 1;
        asm volatile("cp.async.wait_group 0;" ::: "memory");
        __syncthreads();
        if (kc + 1 < KC) issue(kc + 1, buf ^ 1);

#pragma unroll
        for (int s = 0; s < 2; s++) {
            const int ks = s * 16;
            uint32_t a[4][4];
#pragma unroll
            for (int mf = 0; mf < 4; mf++) {
                const __half* ab = &As[buf][(wm + mf * 16 + gid) * APAD + ks];
                a[mf][0] = *reinterpret_cast<const uint32_t*>(&ab[2 * tig]);
                a[mf][1] = *reinterpret_cast<const uint32_t*>(&ab[8 * APAD + 2 * tig]);
                a[mf][2] = *reinterpret_cast<const uint32_t*>(&ab[2 * tig + 8]);
                a[mf][3] = *reinterpret_cast<const uint32_t*>(&ab[8 * APAD + 2 * tig + 8]);
            }
            uint32_t b[4][2];
#pragma unroll
            for (int nf = 0; nf < 4; nf++) {
                const __half* bb = &Bs[buf][(wn + nf * 8 + gid) * APAD + ks];
                b[nf][0] = *reinterpret_cast<const uint32_t*>(&bb[2 * tig]);
                b[nf][1] = *reinterpret_cast<const uint32_t*>(&bb[2 * tig + 8]);
            }
#pragma unroll
            for (int mf = 0; mf < 4; mf++)
#pragma unroll
                for (int nf = 0; nf < 4; nf++) {
                    asm volatile(
                        "mma.sync.aligned.m16n8k16.row.col.f32.f16.f16.f32 "
                        "{%0,%1,%2,%3}, {%4,%5,%6,%7}, {%8,%9}, {%0,%1,%2,%3};"
                        : "+f"(c[mf][nf][0]), "+f"(c[mf][nf][1]),
                          "+f"(c[mf][nf][2]), "+f"(c[mf][nf][3])
                        : "r"(a[mf][0]), "r"(a[mf][1]), "r"(a[mf][2]), "r"(a[mf][3]),
                          "r"(b[nf][0]), "r"(b[nf][1]));
                }
        }
        __syncthreads();
    }

    float bxv[4], byv[4];
#pragma unroll
    for (int nf = 0; nf < 4; nf++) {
        const int cc = wn + nf * 8 + 2 * tig;
        bxv[nf] = bias[cc];
        byv[nf] = bias[cc + 1];
    }
#pragma unroll
    for (int mf = 0; mf < 4; mf++) {
        const int r0 = row0 + wm + mf * 16 + gid;
        float rs0 = rowscale[r0], rs1 = rowscale[r0 + 8];
#pragma unroll
        for (int nf = 0; nf < 4; nf++) {
            const int cc = wn + nf * 8 + 2 * tig;
            __half2 v0 = __floats2half2_rn(fmaxf(c[mf][nf][0] + bxv[nf], 0.f) * rs0,
                                           fmaxf(c[mf][nf][1] + byv[nf], 0.f) * rs0);
            __half2 v1 = __floats2half2_rn(fmaxf(c[mf][nf][2] + bxv[nf], 0.f) * rs1,
                                           fmaxf(c[mf][nf][3] + byv[nf], 0.f) * rs1);
            *reinterpret_cast<__half2*>(&out[(size_t)r0 * 128 + cc]) = v0;
            *reinterpret_cast<__half2*>(&out[(size_t)(r0 + 8) * 128 + cc]) = v1;
        }
    }
}

// ---------------- fused layer-1 GEMM + global max pool ----------------
__global__ void __launch_bounds__(256, 2)
gemm_h_pool_kernel(const __half* __restrict__ A, const __half* __restrict__ Wt,
                   const float* __restrict__ bias, const int* __restrict__ batch,
                   float* __restrict__ pool, int K, int G)
{
    __shared__ __half As[2][128 * APAD];
    __shared__ __half Bs[2][128 * APAD];
    __shared__ unsigned int pool_s[4 * 128];   // up to 4 graph segments per 128-row block

    const int tid  = threadIdx.x;
    const int row0 = blockIdx.x * 128;
    const int lane = tid & 31;
    const int wid  = tid >> 5;
    const int gid  = lane >> 2;
    const int tig  = lane & 3;
    const int wm   = (wid & 1) * 64;
    const int wn   = (wid >> 1) * 32;

    for (int i = tid; i < 4 * 128; i += 256) pool_s[i] = 0u;

    float c[4][4][4];
#pragma unroll
    for (int i = 0; i < 4; i++)
#pragma unroll
        for (int j = 0; j < 4; j++)
#pragma unroll
            for (int r = 0; r < 4; r++) c[i][j][r] = 0.0f;

    const int KC = K >> 5;

    auto issue = [&](int kc, int buf) {
        const int k0 = kc << 5;
#pragma unroll
        for (int rpt = 0; rpt < 2; rpt++) {
            int i = tid + rpt * 256;
            int m = i >> 2, ch = i & 3;
            const __half* src = A + (size_t)(row0 + m) * K + k0 + ch * 8;
            uint32_t dst = (uint32_t)__cvta_generic_to_shared(&As[buf][m * APAD + ch * 8]);
            asm volatile("cp.async.cg.shared.global [%0], [%1], 16;" :: "r"(dst), "l"(src));
        }
#pragma unroll
        for (int rpt = 0; rpt < 2; rpt++) {
            int i = tid + rpt * 256;
            int n = i >> 2, ch = i & 3;
            const __half* src = Wt + (size_t)n * K + k0 + ch * 8;
            uint32_t dst = (uint32_t)__cvta_generic_to_shared(&Bs[buf][n * APAD + ch * 8]);
            asm volatile("cp.async.cg.shared.global [%0], [%1], 16;" :: "r"(dst), "l"(src));
        }
        asm volatile("cp.async.commit_group;" ::: "memory");
    };

    issue(0, 0);

    for (int kc = 0; kc < KC; kc++) {
        const int buf = kc & 1;
        asm volatile("cp.async.wait_group 0;" ::: "memory");
        __syncthreads();
        if (kc + 1 < KC) issue(kc + 1, buf ^ 1);

#pragma unroll
        for (int s = 0; s < 2; s++) {
            const int ks = s * 16;
            uint32_t a[4][4];
#pragma unroll
            for (int mf = 0; mf < 4; mf++) {
                const __half* ab = &As[buf][(wm + mf * 16 + gid) * APAD + ks];
                a[mf][0] = *reinterpret_cast<const uint32_t*>(&ab[2 * tig]);
                a[mf][1] = *reinterpret_cast<const uint32_t*>(&ab[8 * APAD + 2 * tig]);
                a[mf][2] = *reinterpret_cast<const uint32_t*>(&ab[2 * tig + 8]);
                a[mf][3] = *reinterpret_cast<const uint32_t*>(&ab[8 * APAD + 2 * tig + 8]);
            }
            uint32_t b[4][2];
#pragma unroll
            for (int nf = 0; nf < 4; nf++) {
                const __half* bb = &Bs[buf][(wn + nf * 8 + gid) * APAD + ks];
                b[nf][0] = *reinterpret_cast<const uint32_t*>(&bb[2 * tig]);
                b[nf][1] = *reinterpret_cast<const uint32_t*>(&bb[2 * tig + 8]);
            }
#pragma unroll
            for (int mf = 0; mf < 4; mf++)
#pragma unroll
                for (int nf = 0; nf < 4; nf++) {
                    asm volatile(
                        "mma.sync.aligned.m16n8k16.row.col.f32.f16.f16.f32 "
                        "{%0,%1,%2,%3}, {%4,%5,%6,%7}, {%8,%9}, {%0,%1,%2,%3};"
                        : "+f"(c[mf][nf][0]), "+f"(c[mf][nf][1]),
                          "+f"(c[mf][nf][2]), "+f"(c[mf][nf][3])
                        : "r"(a[mf][0]), "r"(a[mf][1]), "r"(a[mf][2]), "r"(a[mf][3]),
                          "r"(b[nf][0]), "r"(b[nf][1]));
                }
        }
        __syncthreads();
    }

    // epilogue: relu(acc+bias) -> per-segment smem max -> global atomicMax
    float bxv[4], byv[4];
#pragma unroll
    for (int nf = 0; nf < 4; nf++) {
        const int cc = wn + nf * 8 + 2 * tig;
        bxv[nf] = bias[cc];
        byv[nf] = bias[cc + 1];
    }
    const int gbase = __ldg(&batch[row0]);
#pragma unroll
    for (int mf = 0; mf < 4; mf++) {
        const int r0 = row0 + wm + mf * 16 + gid;
        const int seg0 = __ldg(&batch[r0]) - gbase;
        const int seg1 = __ldg(&batch[r0 + 8]) - gbase;
#pragma unroll
        for (int nf = 0; nf < 4; nf++) {
            const int cc = wn + nf * 8 + 2 * tig;
            float v00 = fmaxf(c[mf][nf][0] + bxv[nf], 0.f);
            float v01 = fmaxf(c[mf][nf][1] + byv[nf], 0.f);
            float v10 = fmaxf(c[mf][nf][2] + bxv[nf], 0.f);
            float v11 = fmaxf(c[mf][nf][3] + byv[nf], 0.f);
            atomicMax(&pool_s[seg0 * 128 + cc],     __float_as_uint(v00));
            atomicMax(&pool_s[seg0 * 128 + cc + 1], __float_as_uint(v01));
            atomicMax(&pool_s[seg1 * 128 + cc],     __float_as_uint(v10));
            atomicMax(&pool_s[seg1 * 128 + cc + 1], __float_as_uint(v11));
        }
    }
    __syncthreads();
    for (int i = tid; i < 4 * 128; i += 256) {
        int g = gbase + (i >> 7);
        unsigned int v = pool_s[i];
        if (g < G && v != 0u)
            atomicMax(reinterpret_cast<unsigned int*>(&pool[(size_t)g * 128 + (i & 127)]), v);
    }
}

// ---------------- FFMA GEMM for FF head (full fp32): out = relu(A@W + bias) ----------------
__global__ void __launch_bounds__(256, 2)
gemm_ff_kernel(const float* __restrict__ A, const float* __restrict__ W,
               const float* __restrict__ bias, float* __restrict__ out,
               int M, int K, int Nout)
{
    __shared__ float As[16 * 128];
    __shared__ float Bs[16 * 128];

    const int tid  = threadIdx.x;
    const int tx   = tid & 15;
    const int ty   = tid >> 4;
    const int row0 = blockIdx.x * 128;
    const int col0 = blockIdx.y * 128;

    float acc[8][8];
#pragma unroll
    for (int i = 0; i < 8; i++)
#pragma unroll
        for (int j = 0; j < 8; j++) acc[i][j] = 0.0f;

    const int KC = (K + 15) >> 4;
    for (int kc = 0; kc < KC; kc++) {
        const int k0 = kc << 4;
        for (int i = tid; i < 512; i += 256) {
            int m = i >> 2, kv = (i & 3) << 2;
            int row = row0 + m;
            float4 v = make_float4(0.f, 0.f, 0.f, 0.f);
            if (row < M && (k0 + kv) < K)
                v = *reinterpret_cast<const float4*>(&A[(size_t)row * K + k0 + kv]);
            As[(kv + 0) * 128 + m] = v.x;
            As[(kv + 1) * 128 + m] = v.y;
            As[(kv + 2) * 128 + m] = v.z;
            As[(kv + 3) * 128 + m] = v.w;
        }
        for (int i = tid; i < 512; i += 256) {
            int kk = i >> 5, n4 = (i & 31) << 2;
            float4 v = make_float4(0.f, 0.f, 0.f, 0.f);
            if ((k0 + kk) < K)
                v = *reinterpret_cast<const float4*>(&W[(size_t)(k0 + kk) * Nout + col0 + n4]);
            *reinterpret_cast<float4*>(&Bs[kk * 128 + n4]) = v;
        }
        __syncthreads();
#pragma unroll
        for (int kk = 0; kk < 16; kk++) {
            float4 a0 = *reinterpret_cast<const float4*>(&As[kk * 128 + ty * 8]);
            float4 a1 = *reinterpret_cast<const float4*>(&As[kk * 128 + ty * 8 + 4]);
            float4 b0 = *reinterpret_cast<const float4*>(&Bs[kk * 128 + tx * 8]);
            float4 b1 = *reinterpret_cast<const float4*>(&Bs[kk * 128 + tx * 8 + 4]);
            float av[8] = {a0.x, a0.y, a0.z, a0.w, a1.x, a1.y, a1.z, a1.w};
            float bv[8] = {b0.x, b0.y, b0.z, b0.w, b1.x, b1.y, b1.z, b1.w};
#pragma unroll
            for (int i = 0; i < 8; i++)
#pragma unroll
                for (int j = 0; j < 8; j++)
                    acc[i][j] += av[i] * bv[j];
        }
        __syncthreads();
    }

#pragma unroll
    for (int i = 0; i < 8; i++) {
        int row = row0 + ty * 8 + i;
        if (row >= M) break;
        const float4 b0 = *reinterpret_cast<const float4*>(&bias[col0 + tx * 8]);
        const float4 b1 = *reinterpret_cast<const float4*>(&bias[col0 + tx * 8 + 4]);
        float4 v0 = make_float4(fmaxf(acc[i][0] + b0.x, 0.f), fmaxf(acc[i][1] + b0.y, 0.f),
                                fmaxf(acc[i][2] + b0.z, 0.f), fmaxf(acc[i][3] + b0.w, 0.f));
        float4 v1 = make_float4(fmaxf(acc[i][4] + b1.x, 0.f), fmaxf(acc[i][5] + b1.y, 0.f),
                                fmaxf(acc[i][6] + b1.z, 0.f), fmaxf(acc[i][7] + b1.w, 0.f));
        float4* o = reinterpret_cast<float4*>(&out[(size_t)row * Nout + col0 + tx * 8]);
        o[0] = v0; o[1] = v1;
    }
}

// ---------------- launch ----------------
extern "C" void kernel_launch(void* const* d_in, const int* in_sizes, int n_in,
                              void* d_out, int out_size)
{
    const float* x     = (const float*)d_in[0];
    const int*   ei    = (const int*)d_in[1];
    const int*   batch = (const int*)d_in[2];
    const float* W0    = (const float*)d_in[3];
    const float* b0    = (const float*)d_in[4];
    const float* W1    = (const float*)d_in[5];
    const float* b1    = (const float*)d_in[6];
    const float* Wf0   = (const float*)d_in[7];
    const float* bf0   = (const float*)d_in[8];
    const float* Wf1   = (const float*)d_in[9];
    const float* bf1   = (const float*)d_in[10];
    float*       out   = (float*)d_out;

    const int F_IN = 78;
    const int N = in_sizes[0] / F_IN;
    const int E = in_sizes[1] / 2;
    const int G = out_size / HD;

    const int* src = ei;
    const int* dst = ei + E;

    int *p_counts, *p_rowptr, *p_cursor, *p_colidx, *p_bsum, *p_boff;
    float *p_dinv, *p_pool, *p_ff;
    __half *p_xs, *p_ax, *p_hh, *p_ah, *p_w0t, *p_w1t;
    cudaGetSymbolAddress((void**)&p_counts, g_counts);
    cudaGetSymbolAddress((void**)&p_rowptr, g_rowptr);
    cudaGetSymbolAddress((void**)&p_cursor, g_cursor);
    cudaGetSymbolAddress((void**)&p_colidx, g_colidx);
    cudaGetSymbolAddress((void**)&p_bsum,   g_bsum);
    cudaGetSymbolAddress((void**)&p_boff,   g_boff);
    cudaGetSymbolAddress((void**)&p_dinv,   g_dinv);
    cudaGetSymbolAddress((void**)&p_xs,     g_xs);
    cudaGetSymbolAddress((void**)&p_ax,     g_ax);
    cudaGetSymbolAddress((void**)&p_hh,     g_hh);
    cudaGetSymbolAddress((void**)&p_ah,     g_ah);
    cudaGetSymbolAddress((void**)&p_w0t,    g_w0t);
    cudaGetSymbolAddress((void**)&p_w1t,    g_w1t);
    cudaGetSymbolAddress((void**)&p_pool,   g_pool);
    cudaGetSymbolAddress((void**)&p_ff,     g_ff);

    // side stream + events (created once on the uncaptured correctness call)
    static cudaStream_t s2 = nullptr;
    static cudaEvent_t ev_entry = nullptr, ev_dinv = nullptr, ev_conv = nullptr;
    if (!s2) {
        cudaStreamCreateWithFlags(&s2, cudaStreamNonBlocking);
        cudaEventCreateWithFlags(&ev_entry, cudaEventDisableTiming);
        cudaEventCreateWithFlags(&ev_dinv,  cudaEventDisableTiming);
        cudaEventCreateWithFlags(&ev_conv,  cudaEventDisableTiming);
    }

    const int TB = 256;
    int gE = (E + TB - 1) / TB;
    int NB = (N + CHUNK - 1) / CHUNK;
    int gW = (N * 32 + TB - 1) / TB;   // warp-per-node grids

    // ---- fork: side stream does weight conversion + pool zero-init ----
    cudaEventRecord(ev_entry, 0);
    cudaStreamWaitEvent(s2, ev_entry, 0);
    conv_w_kernel<<<(128 * 96 + 128 * 128 + TB - 1) / TB, TB, 0, s2>>>(W0, W1, p_w0t, p_w1t);
    cudaMemsetAsync(p_pool, 0, (size_t)G * HD * sizeof(float), s2);

    // ---- main stream: CSR build + norm ----
    cudaMemsetAsync(p_counts, 0, (size_t)N * sizeof(int));
    count_deg_kernel<<<gE, TB>>>(dst, p_counts, E);
    scan_chunk_sum<<<NB, 256>>>(p_counts, p_bsum, p_dinv, N);
    cudaEventRecord(ev_dinv, 0);              // dinv ready -> conv_x can start on s2
    cudaStreamWaitEvent(s2, ev_dinv, 0);
    conv_x_kernel<<<(N * 39 + TB - 1) / TB, TB, 0, s2>>>(
        (const float2*)x, p_dinv, (__half2*)p_xs, N);
    cudaEventRecord(ev_conv, s2);

    scan_bsum<<<1, 512>>>(p_bsum, p_boff, NB);
    scan_final<<<NB, CHUNK>>>(p_counts, p_boff, p_rowptr, p_cursor, N);
    fill_csr_kernel<<<gE, TB>>>(src, dst, p_cursor, p_colidx, E);

    // ---- join: agg0 needs xs (s2) + CSR (main); gemm needs w0t (s2) ----
    cudaStreamWaitEvent(0, ev_conv, 0);

    // ---- layer 0: aggregate-then-transform; GEMM stores h0*dinv ----
    agg0_kernel<<<gW, TB>>>((const uint2*)p_xs, p_rowptr, p_colidx, p_dinv, (uint2*)p_ax, N);
    gemm_h_kernel<<<N / 128, TB>>>(p_ax, p_w0t, b0, p_dinv, p_hh, 96);

    // ---- layer 1: agg + fused GEMM/max-pool (h1 never materialized) ----
    agg1_kernel<<<gW, TB>>>((const uint2*)p_hh, p_rowptr, p_colidx, p_dinv, (uint2*)p_ah, N);
    gemm_h_pool_kernel<<<N / 128, TB>>>(p_ah, p_w1t, b1, batch, p_pool, 128, G);

    // ---- FF head (fp32) ----
    {
        dim3 grid((G + 127) / 128, 2);
        gemm_ff_kernel<<<grid, TB>>>(p_pool, Wf0, bf0, p_ff, G, HD, 256);
    }
    {
        dim3 grid((G + 127) / 128, 1);
        gemm_ff_kernel<<<grid, TB>>>(p_ff, Wf1, bf1, out, G, 256, HD);
    }
}

// round 16
// speedup vs baseline: 1.0548x; 1.0307x over previous
#include <cuda_runtime.h>
#include <cuda_fp16.h>
#include <cstdint>

#define NMAX 400000
#define EMAX 1600000
#define GMAX 4096
#define HD   128
#define CHUNK 1024

#define APAD 40    // smem row stride in halves (32 data + 8 pad)

// -------- device scratch --------
__device__ int    g_counts [NMAX];
__device__ int    g_rowptr [NMAX + 1];
__device__ int    g_cursor [NMAX];
__device__ int    g_colidx [EMAX];
__device__ int    g_bsum   [512];
__device__ int    g_boff   [512];
__device__ float  g_dinv   [NMAX];
__device__ __half g_xs     [(size_t)NMAX * 80];    // x*dinv fp16, stride 80 (cols 78,79 = 0)
__device__ __half g_ax     [(size_t)NMAX * 96];    // layer-0 agg out, stride 96 (cols 78..95 = 0)
__device__ __half g_hh     [(size_t)NMAX * 128];   // h0*dinv after layer0 GEMM
__device__ __half g_ah     [(size_t)NMAX * 128];   // layer-1 agg out
__device__ __half g_w0t    [128 * 96];             // W0^T fp16 [n][k], k padded to 96
__device__ __half g_w1t    [128 * 128];            // W1^T fp16 [n][k]
__device__ float  g_pool   [(size_t)GMAX * HD];
__device__ float  g_ff     [(size_t)GMAX * 256];

// unpack uint2 (4 halves) and accumulate into float4
__device__ __forceinline__ void acc_u2(uint2 v, float4& a) {
    float2 f0 = __half22float2(*reinterpret_cast<__half2*>(&v.x));
    float2 f1 = __half22float2(*reinterpret_cast<__half2*>(&v.y));
    a.x += f0.x; a.y += f0.y; a.z += f1.x; a.w += f1.y;
}

__device__ __forceinline__ uint2 pack_f4(float4 a, float s) {
    uint2 o;
    __half2 h0 = __floats2half2_rn(a.x * s, a.y * s);
    __half2 h1 = __floats2half2_rn(a.z * s, a.w * s);
    o.x = *reinterpret_cast<uint32_t*>(&h0);
    o.y = *reinterpret_cast<uint32_t*>(&h1);
    return o;
}

// ---------------- degree / CSR build ----------------
__global__ void count_deg_kernel(const int* __restrict__ dst, int* counts, int E) {
    int e = blockIdx.x * blockDim.x + threadIdx.x;
    if (e < E) atomicAdd(&counts[dst[e]], 1);
}

__global__ void scan_chunk_sum(const int* __restrict__ counts, int* bsum,
                               float* __restrict__ dinv, int N) {
    __shared__ int sh[256];
    int base = blockIdx.x * CHUNK;
    int s = 0;
    for (int i = threadIdx.x; i < CHUNK; i += 256) {
        int g = base + i;
        int c = (g < N) ? counts[g] : 0;
        s += c;
        if (g < N) dinv[g] = rsqrtf((float)c + 1.0f);
    }
    sh[threadIdx.x] = s; __syncthreads();
    for (int o = 128; o > 0; o >>= 1) {
        if (threadIdx.x < o) sh[threadIdx.x] += sh[threadIdx.x + o];
        __syncthreads();
    }
    if (threadIdx.x == 0) bsum[blockIdx.x] = sh[0];
}

__global__ void scan_bsum(const int* __restrict__ bsum, int* boff, int NB) {
    __shared__ int sh[512];
    int v = (threadIdx.x < NB) ? bsum[threadIdx.x] : 0;
    sh[threadIdx.x] = v; __syncthreads();
    for (int o = 1; o < 512; o <<= 1) {
        int t = (threadIdx.x >= o) ? sh[threadIdx.x - o] : 0;
        __syncthreads();
        sh[threadIdx.x] += t;
        __syncthreads();
    }
    if (threadIdx.x < NB) boff[threadIdx.x] = sh[threadIdx.x] - v;  // exclusive
}

__global__ void scan_final(const int* __restrict__ counts, const int* __restrict__ boff,
                           int* rowptr, int* cursor, int N) {
    __shared__ int sh[CHUNK];
    int g = blockIdx.x * CHUNK + threadIdx.x;
    int v = (g < N) ? counts[g] : 0;
    sh[threadIdx.x] = v; __syncthreads();
    for (int o = 1; o < CHUNK; o <<= 1) {
        int t = (threadIdx.x >= o) ? sh[threadIdx.x - o] : 0;
        __syncthreads();
        sh[threadIdx.x] += t;
        __syncthreads();
    }
    if (g < N) {
        int excl = boff[blockIdx.x] + sh[threadIdx.x] - v;
        rowptr[g] = excl;
        cursor[g] = excl;
        if (g == N - 1) rowptr[N] = boff[blockIdx.x] + sh[threadIdx.x];
    }
}

__global__ void fill_csr_kernel(const int* __restrict__ src, const int* __restrict__ dst,
                                int* cursor, int* colidx, int E) {
    int e = blockIdx.x * blockDim.x + threadIdx.x;
    if (e < E) {
        int d = dst[e];
        int p = atomicAdd(&cursor[d], 1);
        colidx[p] = src[e];
    }
}

// ---------------- conversions ----------------
// one uint2 (4 halves) per thread: i = n*20 + c covers half2 cols 2c, 2c+1
__global__ void conv_x_kernel(const float2* __restrict__ x2, const float* __restrict__ dinv,
                              uint2* __restrict__ xsv, int N) {
    int i = blockIdx.x * blockDim.x + threadIdx.x;   // over N*20 uint2
    if (i >= N * 20) return;
    int n = i / 20;
    int c = i - n * 20;
    float dd = __ldg(&dinv[n]);
    const float2* row = x2 + (size_t)n * 39;
    float2 v0 = __ldg(&row[2 * c]);
    float2 v1 = (c < 19) ? __ldg(&row[2 * c + 1]) : make_float2(0.f, 0.f);
    __half2 h0 = __floats2half2_rn(v0.x * dd, v0.y * dd);
    __half2 h1 = __floats2half2_rn(v1.x * dd, v1.y * dd);
    uint2 o;
    o.x = *reinterpret_cast<uint32_t*>(&h0);
    o.y = *reinterpret_cast<uint32_t*>(&h1);
    xsv[i] = o;
}

__global__ void conv_w_kernel(const float* __restrict__ W0, const float* __restrict__ W1,
                              __half* __restrict__ W0t, __half* __restrict__ W1t) {
    int i = blockIdx.x * blockDim.x + threadIdx.x;
    if (i < 128 * 96) {
        int n = i / 96;
        int k = i - n * 96;
        W0t[i] = (k < 78) ? __float2half_rn(W0[(size_t)k * 128 + n]) : __float2half_rn(0.0f);
    } else if (i < 128 * 96 + 128 * 128) {
        int j = i - 128 * 96;
        int n = j >> 7;
        int k = j & 127;
        W1t[j] = __float2half_rn(W1[(size_t)k * 128 + n]);
    }
}

// ---------------- agg0: ax[d] = h16( dinv[d]*(xs[d] + sum_{s} xs[s]) ), xs already *dinv ----------------
__global__ void agg0_kernel(const uint2* __restrict__ xsv, const int* __restrict__ rowptr,
                            const int* __restrict__ colidx, const float* __restrict__ dinv,
                            uint2* __restrict__ axv, int N)
{
    int w = (blockIdx.x * blockDim.x + threadIdx.x) >> 5;
    int lane = threadIdx.x & 31;
    if (w >= N) return;
    const bool act = lane < 20;

    float4 a = make_float4(0.f, 0.f, 0.f, 0.f);
    if (act) acc_u2(__ldg(&xsv[(size_t)w * 20 + lane]), a);

    int s0 = __ldg(&rowptr[w]);
    int s1 = __ldg(&rowptr[w + 1]);
    int e = s0;
    for (; e + 4 <= s1; e += 4) {
        int i0 = __ldg(&colidx[e + 0]);
        int i1 = __ldg(&colidx[e + 1]);
        int i2 = __ldg(&colidx[e + 2]);
        int i3 = __ldg(&colidx[e + 3]);
        if (act) {
            uint2 u0 = __ldg(&xsv[(size_t)i0 * 20 + lane]);
            uint2 u1 = __ldg(&xsv[(size_t)i1 * 20 + lane]);
            uint2 u2 = __ldg(&xsv[(size_t)i2 * 20 + lane]);
            uint2 u3 = __ldg(&xsv[(size_t)i3 * 20 + lane]);
            acc_u2(u0, a); acc_u2(u1, a); acc_u2(u2, a); acc_u2(u3, a);
        }
    }
    for (; e < s1; e++) {
        int s = __ldg(&colidx[e]);
        if (act) acc_u2(__ldg(&xsv[(size_t)s * 20 + lane]), a);
    }

    float dd = __ldg(&dinv[w]);
    if (act)
        axv[(size_t)w * 24 + lane] = pack_f4(a, dd);
    else if (lane < 24)
        axv[(size_t)w * 24 + lane] = make_uint2(0u, 0u);   // pad halves 80..95
}

// ---------------- agg1 (128-dim): ah[d] = h16( dinv[d]*(hs[d] + sum_{s} hs[s]) ), hs = h0*dinv ----------------
__global__ void agg1_kernel(const uint2* __restrict__ hsv, const int* __restrict__ rowptr,
                            const int* __restrict__ colidx, const float* __restrict__ dinv,
                            uint2* __restrict__ ahv, int N)
{
    int w = (blockIdx.x * blockDim.x + threadIdx.x) >> 5;
    int lane = threadIdx.x & 31;
    if (w >= N) return;

    float4 a = make_float4(0.f, 0.f, 0.f, 0.f);
    acc_u2(__ldg(&hsv[(size_t)w * 32 + lane]), a);

    int s0 = __ldg(&rowptr[w]);
    int s1 = __ldg(&rowptr[w + 1]);
    int e = s0;
    for (; e + 4 <= s1; e += 4) {
        int i0 = __ldg(&colidx[e + 0]);
        int i1 = __ldg(&colidx[e + 1]);
        int i2 = __ldg(&colidx[e + 2]);
        int i3 = __ldg(&colidx[e + 3]);
        uint2 u0 = __ldg(&hsv[(size_t)i0 * 32 + lane]);
        uint2 u1 = __ldg(&hsv[(size_t)i1 * 32 + lane]);
        uint2 u2 = __ldg(&hsv[(size_t)i2 * 32 + lane]);
        uint2 u3 = __ldg(&hsv[(size_t)i3 * 32 + lane]);
        acc_u2(u0, a); acc_u2(u1, a); acc_u2(u2, a); acc_u2(u3, a);
    }
    for (; e < s1; e++) {
        int s = __ldg(&colidx[e]);
        acc_u2(__ldg(&hsv[(size_t)s * 32 + lane]), a);
    }

    float dd = __ldg(&dinv[w]);
    ahv[(size_t)w * 32 + lane] = pack_f4(a, dd);
}

// ---------------- fp16 tensor-core GEMM (layer 0): hh = h16(relu(A@Wt^T + bias) * rowscale) ----------------
__global__ void __launch_bounds__(256, 2)
gemm_h_kernel(const __half* __restrict__ A, const __half* __restrict__ Wt,
              const float* __restrict__ bias, const float* __restrict__ rowscale,
              __half* __restrict__ out, int K)
{
    __shared__ __half As[2][128 * APAD];
    __shared__ __half Bs[2][128 * APAD];

    const int tid  = threadIdx.x;
    const int row0 = blockIdx.x * 128;
    const int lane = tid & 31;
    const int wid  = tid >> 5;
    const int gid  = lane >> 2;
    const int tig  = lane & 3;
    const int wm   = (wid & 1) * 64;
    const int wn   = (wid >> 1) * 32;

    float c[4][4][4];
#pragma unroll
    for (int i = 0; i < 4; i++)
#pragma unroll
        for (int j = 0; j < 4; j++)
#pragma unroll
            for (int r = 0; r < 4; r++) c[i][j][r] = 0.0f;

    const int KC = K >> 5;

    auto issue = [&](int kc, int buf) {
        const int k0 = kc << 5;
#pragma unroll
        for (int rpt = 0; rpt < 2; rpt++) {
            int i = tid + rpt * 256;
            int m = i >> 2, ch = i & 3;
            const __half* src = A + (size_t)(row0 + m) * K + k0 + ch * 8;
            uint32_t dst = (uint32_t)__cvta_generic_to_shared(&As[buf][m * APAD + ch * 8]);
            asm volatile("cp.async.cg.shared.global [%0], [%1], 16;" :: "r"(dst), "l"(src));
        }
#pragma unroll
        for (int rpt = 0; rpt < 2; rpt++) {
            int i = tid + rpt * 256;
            int n = i >> 2, ch = i & 3;
            const __half* src = Wt + (size_t)n * K + k0 + ch * 8;
            uint32_t dst = (uint32_t)__cvta_generic_to_shared(&Bs[buf][n * APAD + ch * 8]);
            asm volatile("cp.async.cg.shared.global [%0], [%1], 16;" :: "r"(dst), "l"(src));
        }
        asm volatile("cp.async.commit_group;" ::: "memory");
    };

    issue(0, 0);

    for (int kc = 0; kc < KC; kc++) {
        const int buf = kc & 1;
        asm volatile("cp.async.wait_group 0;" ::: "memory");
        __syncthreads();
        if (kc + 1 < KC) issue(kc + 1, buf ^ 1);

#pragma unroll
        for (int s = 0; s < 2; s++) {
            const int ks = s * 16;
            uint32_t a[4][4];
#pragma unroll
            for (int mf = 0; mf < 4; mf++) {
                const __half* ab = &As[buf][(wm + mf * 16 + gid) * APAD + ks];
                a[mf][0] = *reinterpret_cast<const uint32_t*>(&ab[2 * tig]);
                a[mf][1] = *reinterpret_cast<const uint32_t*>(&ab[8 * APAD + 2 * tig]);
                a[mf][2] = *reinterpret_cast<const uint32_t*>(&ab[2 * tig + 8]);
                a[mf][3] = *reinterpret_cast<const uint32_t*>(&ab[8 * APAD + 2 * tig + 8]);
            }
            uint32_t b[4][2];
#pragma unroll
            for (int nf = 0; nf < 4; nf++) {
                const __half* bb = &Bs[buf][(wn + nf * 8 + gid) * APAD + ks];
                b[nf][0] = *reinterpret_cast<const uint32_t*>(&bb[2 * tig]);
                b[nf][1] = *reinterpret_cast<const uint32_t*>(&bb[2 * tig + 8]);
            }
#pragma unroll
            for (int mf = 0; mf < 4; mf++)
#pragma unroll
                for (int nf = 0; nf < 4; nf++) {
                    asm volatile(
                        "mma.sync.aligned.m16n8k16.row.col.f32.f16.f16.f32 "
                        "{%0,%1,%2,%3}, {%4,%5,%6,%7}, {%8,%9}, {%0,%1,%2,%3};"
                        : "+f"(c[mf][nf][0]), "+f"(c[mf][nf][1]),
                          "+f"(c[mf][nf][2]), "+f"(c[mf][nf][3])
                        : "r"(a[mf][0]), "r"(a[mf][1]), "r"(a[mf][2]), "r"(a[mf][3]),
                          "r"(b[nf][0]), "r"(b[nf][1]));
                }
        }
        __syncthreads();
    }

    float bxv[4], byv[4];
#pragma unroll
    for (int nf = 0; nf < 4; nf++) {
        const int cc = wn + nf * 8 + 2 * tig;
        bxv[nf] = bias[cc];
        byv[nf] = bias[cc + 1];
    }
#pragma unroll
    for (int mf = 0; mf < 4; mf++) {
        const int r0 = row0 + wm + mf * 16 + gid;
        float rs0 = rowscale[r0], rs1 = rowscale[r0 + 8];
#pragma unroll
        for (int nf = 0; nf < 4; nf++) {
            const int cc = wn + nf * 8 + 2 * tig;
            __half2 v0 = __floats2half2_rn(fmaxf(c[mf][nf][0] + bxv[nf], 0.f) * rs0,
                                           fmaxf(c[mf][nf][1] + byv[nf], 0.f) * rs0);
            __half2 v1 = __floats2half2_rn(fmaxf(c[mf][nf][2] + bxv[nf], 0.f) * rs1,
                                           fmaxf(c[mf][nf][3] + byv[nf], 0.f) * rs1);
            *reinterpret_cast<__half2*>(&out[(size_t)r0 * 128 + cc]) = v0;
            *reinterpret_cast<__half2*>(&out[(size_t)(r0 + 8) * 128 + cc]) = v1;
        }
    }
}

// ---------------- fused layer-1 GEMM + global max pool ----------------
__global__ void __launch_bounds__(256, 2)
gemm_h_pool_kernel(const __half* __restrict__ A, const __half* __restrict__ Wt,
                   const float* __restrict__ bias, const int* __restrict__ batch,
                   float* __restrict__ pool, int K, int G)
{
    __shared__ __half As[2][128 * APAD];
    __shared__ __half Bs[2][128 * APAD];
    __shared__ unsigned int pool_s[4 * 128];   // up to 4 graph segments per 128-row block

    const int tid  = threadIdx.x;
    const int row0 = blockIdx.x * 128;
    const int lane = tid & 31;
    const int wid  = tid >> 5;
    const int gid  = lane >> 2;
    const int tig  = lane & 3;
    const int wm   = (wid & 1) * 64;
    const int wn   = (wid >> 1) * 32;

    for (int i = tid; i < 4 * 128; i += 256) pool_s[i] = 0u;

    float c[4][4][4];
#pragma unroll
    for (int i = 0; i < 4; i++)
#pragma unroll
        for (int j = 0; j < 4; j++)
#pragma unroll
            for (int r = 0; r < 4; r++) c[i][j][r] = 0.0f;

    const int KC = K >> 5;

    auto issue = [&](int kc, int buf) {
        const int k0 = kc << 5;
#pragma unroll
        for (int rpt = 0; rpt < 2; rpt++) {
            int i = tid + rpt * 256;
            int m = i >> 2, ch = i & 3;
            const __half* src = A + (size_t)(row0 + m) * K + k0 + ch * 8;
            uint32_t dst = (uint32_t)__cvta_generic_to_shared(&As[buf][m * APAD + ch * 8]);
            asm volatile("cp.async.cg.shared.global [%0], [%1], 16;" :: "r"(dst), "l"(src));
        }
#pragma unroll
        for (int rpt = 0; rpt < 2; rpt++) {
            int i = tid + rpt * 256;
            int n = i >> 2, ch = i & 3;
            const __half* src = Wt + (size_t)n * K + k0 + ch * 8;
            uint32_t dst = (uint32_t)__cvta_generic_to_shared(&Bs[buf][n * APAD + ch * 8]);
            asm volatile("cp.async.cg.shared.global [%0], [%1], 16;" :: "r"(dst), "l"(src));
        }
        asm volatile("cp.async.commit_group;" ::: "memory");
    };

    issue(0, 0);

    for (int kc = 0; kc < KC; kc++) {
        const int buf = kc & 1;
        asm volatile("cp.async.wait_group 0;" ::: "memory");
        __syncthreads();
        if (kc + 1 < KC) issue(kc + 1, buf ^ 1);

#pragma unroll
        for (int s = 0; s < 2; s++) {
            const int ks = s * 16;
            uint32_t a[4][4];
#pragma unroll
            for (int mf = 0; mf < 4; mf++) {
                const __half* ab = &As[buf][(wm + mf * 16 + gid) * APAD + ks];
                a[mf][0] = *reinterpret_cast<const uint32_t*>(&ab[2 * tig]);
                a[mf][1] = *reinterpret_cast<const uint32_t*>(&ab[8 * APAD + 2 * tig]);
                a[mf][2] = *reinterpret_cast<const uint32_t*>(&ab[2 * tig + 8]);
                a[mf][3] = *reinterpret_cast<const uint32_t*>(&ab[8 * APAD + 2 * tig + 8]);
            }
            uint32_t b[4][2];
#pragma unroll
            for (int nf = 0; nf < 4; nf++) {
                const __half* bb = &Bs[buf][(wn + nf * 8 + gid) * APAD + ks];
                b[nf][0] = *reinterpret_cast<const uint32_t*>(&bb[2 * tig]);
                b[nf][1] = *reinterpret_cast<const uint32_t*>(&bb[2 * tig + 8]);
            }
#pragma unroll
            for (int mf = 0; mf < 4; mf++)
#pragma unroll
                for (int nf = 0; nf < 4; nf++) {
                    asm volatile(
                        "mma.sync.aligned.m16n8k16.row.col.f32.f16.f16.f32 "
                        "{%0,%1,%2,%3}, {%4,%5,%6,%7}, {%8,%9}, {%0,%1,%2,%3};"
                        : "+f"(c[mf][nf][0]), "+f"(c[mf][nf][1]),
                          "+f"(c[mf][nf][2]), "+f"(c[mf][nf][3])
                        : "r"(a[mf][0]), "r"(a[mf][1]), "r"(a[mf][2]), "r"(a[mf][3]),
                          "r"(b[nf][0]), "r"(b[nf][1]));
                }
        }
        __syncthreads();
    }

    // epilogue: relu(acc+bias) -> per-segment smem max -> global atomicMax
    float bxv[4], byv[4];
#pragma unroll
    for (int nf = 0; nf < 4; nf++) {
        const int cc = wn + nf * 8 + 2 * tig;
        bxv[nf] = bias[cc];
        byv[nf] = bias[cc + 1];
    }
    const int gbase = __ldg(&batch[row0]);
#pragma unroll
    for (int mf = 0; mf < 4; mf++) {
        const int r0 = row0 + wm + mf * 16 + gid;
        const int seg0 = __ldg(&batch[r0]) - gbase;
        const int seg1 = __ldg(&batch[r0 + 8]) - gbase;
#pragma unroll
        for (int nf = 0; nf < 4; nf++) {
            const int cc = wn + nf * 8 + 2 * tig;
            float v00 = fmaxf(c[mf][nf][0] + bxv[nf], 0.f);
            float v01 = fmaxf(c[mf][nf][1] + byv[nf], 0.f);
            float v10 = fmaxf(c[mf][nf][2] + bxv[nf], 0.f);
            float v11 = fmaxf(c[mf][nf][3] + byv[nf], 0.f);
            atomicMax(&pool_s[seg0 * 128 + cc],     __float_as_uint(v00));
            atomicMax(&pool_s[seg0 * 128 + cc + 1], __float_as_uint(v01));
            atomicMax(&pool_s[seg1 * 128 + cc],     __float_as_uint(v10));
            atomicMax(&pool_s[seg1 * 128 + cc + 1], __float_as_uint(v11));
        }
    }
    __syncthreads();
    for (int i = tid; i < 4 * 128; i += 256) {
        int g = gbase + (i >> 7);
        unsigned int v = pool_s[i];
        if (g < G && v != 0u)
            atomicMax(reinterpret_cast<unsigned int*>(&pool[(size_t)g * 128 + (i & 127)]), v);
    }
}

// ---------------- FFMA GEMM for FF head (full fp32): out = relu(A@W + bias) ----------------
__global__ void __launch_bounds__(256, 2)
gemm_ff_kernel(const float* __restrict__ A, const float* __restrict__ W,
               const float* __restrict__ bias, float* __restrict__ out,
               int M, int K, int Nout)
{
    __shared__ float As[16 * 128];
    __shared__ float Bs[16 * 128];

    const int tid  = threadIdx.x;
    const int tx   = tid & 15;
    const int ty   = tid >> 4;
    const int row0 = blockIdx.x * 128;
    const int col0 = blockIdx.y * 128;

    float acc[8][8];
#pragma unroll
    for (int i = 0; i < 8; i++)
#pragma unroll
        for (int j = 0; j < 8; j++) acc[i][j] = 0.0f;

    const int KC = (K + 15) >> 4;
    for (int kc = 0; kc < KC; kc++) {
        const int k0 = kc << 4;
        for (int i = tid; i < 512; i += 256) {
            int m = i >> 2, kv = (i & 3) << 2;
            int row = row0 + m;
            float4 v = make_float4(0.f, 0.f, 0.f, 0.f);
            if (row < M && (k0 + kv) < K)
                v = *reinterpret_cast<const float4*>(&A[(size_t)row * K + k0 + kv]);
            As[(kv + 0) * 128 + m] = v.x;
            As[(kv + 1) * 128 + m] = v.y;
            As[(kv + 2) * 128 + m] = v.z;
            As[(kv + 3) * 128 + m] = v.w;
        }
        for (int i = tid; i < 512; i += 256) {
            int kk = i >> 5, n4 = (i & 31) << 2;
            float4 v = make_float4(0.f, 0.f, 0.f, 0.f);
            if ((k0 + kk) < K)
                v = *reinterpret_cast<const float4*>(&W[(size_t)(k0 + kk) * Nout + col0 + n4]);
            *reinterpret_cast<float4*>(&Bs[kk * 128 + n4]) = v;
        }
        __syncthreads();
#pragma unroll
        for (int kk = 0; kk < 16; kk++) {
            float4 a0 = *reinterpret_cast<const float4*>(&As[kk * 128 + ty * 8]);
            float4 a1 = *reinterpret_cast<const float4*>(&As[kk * 128 + ty * 8 + 4]);
            float4 b0 = *reinterpret_cast<const float4*>(&Bs[kk * 128 + tx * 8]);
            float4 b1 = *reinterpret_cast<const float4*>(&Bs[kk * 128 + tx * 8 + 4]);
            float av[8] = {a0.x, a0.y, a0.z, a0.w, a1.x, a1.y, a1.z, a1.w};
            float bv[8] = {b0.x, b0.y, b0.z, b0.w, b1.x, b1.y, b1.z, b1.w};
#pragma unroll
            for (int i = 0; i < 8; i++)
#pragma unroll
                for (int j = 0; j < 8; j++)
                    acc[i][j] += av[i] * bv[j];
        }
        __syncthreads();
    }

#pragma unroll
    for (int i = 0; i < 8; i++) {
        int row = row0 + ty * 8 + i;
        if (row >= M) break;
        const float4 b0 = *reinterpret_cast<const float4*>(&bias[col0 + tx * 8]);
        const float4 b1 = *reinterpret_cast<const float4*>(&bias[col0 + tx * 8 + 4]);
        float4 v0 = make_float4(fmaxf(acc[i][0] + b0.x, 0.f), fmaxf(acc[i][1] + b0.y, 0.f),
                                fmaxf(acc[i][2] + b0.z, 0.f), fmaxf(acc[i][3] + b0.w, 0.f));
        float4 v1 = make_float4(fmaxf(acc[i][4] + b1.x, 0.f), fmaxf(acc[i][5] + b1.y, 0.f),
                                fmaxf(acc[i][6] + b1.z, 0.f), fmaxf(acc[i][7] + b1.w, 0.f));
        float4* o = reinterpret_cast<float4*>(&out[(size_t)row * Nout + col0 + tx * 8]);
        o[0] = v0; o[1] = v1;
    }
}

// ---------------- launch ----------------
extern "C" void kernel_launch(void* const* d_in, const int* in_sizes, int n_in,
                              void* d_out, int out_size)
{
    const float* x     = (const float*)d_in[0];
    const int*   ei    = (const int*)d_in[1];
    const int*   batch = (const int*)d_in[2];
    const float* W0    = (const float*)d_in[3];
    const float* b0    = (const float*)d_in[4];
    const float* W1    = (const float*)d_in[5];
    const float* b1    = (const float*)d_in[6];
    const float* Wf0   = (const float*)d_in[7];
    const float* bf0   = (const float*)d_in[8];
    const float* Wf1   = (const float*)d_in[9];
    const float* bf1   = (const float*)d_in[10];
    float*       out   = (float*)d_out;

    const int F_IN = 78;
    const int N = in_sizes[0] / F_IN;
    const int E = in_sizes[1] / 2;
    const int G = out_size / HD;

    const int* src = ei;
    const int* dst = ei + E;

    int *p_counts, *p_rowptr, *p_cursor, *p_colidx, *p_bsum, *p_boff;
    float *p_dinv, *p_pool, *p_ff;
    __half *p_xs, *p_ax, *p_hh, *p_ah, *p_w0t, *p_w1t;
    cudaGetSymbolAddress((void**)&p_counts, g_counts);
    cudaGetSymbolAddress((void**)&p_rowptr, g_rowptr);
    cudaGetSymbolAddress((void**)&p_cursor, g_cursor);
    cudaGetSymbolAddress((void**)&p_colidx, g_colidx);
    cudaGetSymbolAddress((void**)&p_bsum,   g_bsum);
    cudaGetSymbolAddress((void**)&p_boff,   g_boff);
    cudaGetSymbolAddress((void**)&p_dinv,   g_dinv);
    cudaGetSymbolAddress((void**)&p_xs,     g_xs);
    cudaGetSymbolAddress((void**)&p_ax,     g_ax);
    cudaGetSymbolAddress((void**)&p_hh,     g_hh);
    cudaGetSymbolAddress((void**)&p_ah,     g_ah);
    cudaGetSymbolAddress((void**)&p_w0t,    g_w0t);
    cudaGetSymbolAddress((void**)&p_w1t,    g_w1t);
    cudaGetSymbolAddress((void**)&p_pool,   g_pool);
    cudaGetSymbolAddress((void**)&p_ff,     g_ff);

    // side stream + events (created once on the uncaptured correctness call)
    static cudaStream_t s2 = nullptr;
    static cudaEvent_t ev_entry = nullptr, ev_dinv = nullptr, ev_conv = nullptr;
    if (!s2) {
        cudaStreamCreateWithFlags(&s2, cudaStreamNonBlocking);
        cudaEventCreateWithFlags(&ev_entry, cudaEventDisableTiming);
        cudaEventCreateWithFlags(&ev_dinv,  cudaEventDisableTiming);
        cudaEventCreateWithFlags(&ev_conv,  cudaEventDisableTiming);
    }

    const int TB = 256;
    int gE = (E + TB - 1) / TB;
    int NB = (N + CHUNK - 1) / CHUNK;
    int gW = (N * 32 + TB - 1) / TB;   // warp-per-node grids

    // ---- fork: side stream does weight conversion + pool zero-init ----
    cudaEventRecord(ev_entry, 0);
    cudaStreamWaitEvent(s2, ev_entry, 0);
    conv_w_kernel<<<(128 * 96 + 128 * 128 + TB - 1) / TB, TB, 0, s2>>>(W0, W1, p_w0t, p_w1t);
    cudaMemsetAsync(p_pool, 0, (size_t)G * HD * sizeof(float), s2);

    // ---- main stream: CSR build + norm ----
    cudaMemsetAsync(p_counts, 0, (size_t)N * sizeof(int));
    count_deg_kernel<<<gE, TB>>>(dst, p_counts, E);
    scan_chunk_sum<<<NB, 256>>>(p_counts, p_bsum, p_dinv, N);
    cudaEventRecord(ev_dinv, 0);              // dinv ready -> conv_x can start on s2
    cudaStreamWaitEvent(s2, ev_dinv, 0);
    conv_x_kernel<<<(N * 20 + TB - 1) / TB, TB, 0, s2>>>(
        (const float2*)x, p_dinv, (uint2*)p_xs, N);
    cudaEventRecord(ev_conv, s2);

    scan_bsum<<<1, 512>>>(p_bsum, p_boff, NB);
    scan_final<<<NB, CHUNK>>>(p_counts, p_boff, p_rowptr, p_cursor, N);
    fill_csr_kernel<<<gE, TB>>>(src, dst, p_cursor, p_colidx, E);

    // ---- join: agg0 needs xs (s2) + CSR (main); gemm needs w0t (s2) ----
    cudaStreamWaitEvent(0, ev_conv, 0);

    // ---- layer 0: aggregate-then-transform; GEMM stores h0*dinv ----
    agg0_kernel<<<gW, TB>>>((const uint2*)p_xs, p_rowptr, p_colidx, p_dinv, (uint2*)p_ax, N);
    gemm_h_kernel<<<N / 128, TB>>>(p_ax, p_w0t, b0, p_dinv, p_hh, 96);

    // ---- layer 1: agg + fused GEMM/max-pool (h1 never materialized) ----
    agg1_kernel<<<gW, TB>>>((const uint2*)p_hh, p_rowptr, p_colidx, p_dinv, (uint2*)p_ah, N);
    gemm_h_pool_kernel<<<N / 128, TB>>>(p_ah, p_w1t, b1, batch, p_pool, 128, G);

    // ---- FF head (fp32) ----
    {
        dim3 grid((G + 127) / 128, 2);
        gemm_ff_kernel<<<grid, TB>>>(p_pool, Wf0, bf0, p_ff, G, HD, 256);
    }
    {
        dim3 grid((G + 127) / 128, 1);
        gemm_ff_kernel<<<grid, TB>>>(p_ff, Wf1, bf1, out, G, 256, HD);
    }
}

// round 17
// speedup vs baseline: 1.0926x; 1.0358x over previous
#include <cuda_runtime.h>
#include <cuda_fp16.h>
#include <cstdint>

#define NMAX 400000
#define EMAX 1600000
#define GMAX 4096
#define HD   128
#define CHUNK 1024

#define APAD 40    // smem row stride in halves (32 data + 8 pad)

// -------- device scratch --------
__device__ int    g_counts [NMAX];
__device__ int    g_rowptr [NMAX + 1];
__device__ int    g_cursor [NMAX];
__device__ int    g_colidx [EMAX];
__device__ int    g_bsum   [512];
__device__ int    g_boff   [512];
__device__ float  g_dinv   [NMAX];
__device__ __half g_xs     [(size_t)NMAX * 80];    // x*dinv fp16, stride 80 (cols 78,79 = 0)
__device__ __half g_ax     [(size_t)NMAX * 96];    // layer-0 agg out, stride 96 (cols 78..95 = 0)
__device__ __half g_hh     [(size_t)NMAX * 128];   // h0*dinv after layer0 GEMM
__device__ __half g_ah     [(size_t)NMAX * 128];   // layer-1 agg out
__device__ __half g_w0t    [128 * 96];             // W0^T fp16 [n][k], k padded to 96
__device__ __half g_w1t    [128 * 128];            // W1^T fp16 [n][k]
__device__ float  g_pool   [(size_t)GMAX * HD];
__device__ float  g_ff     [(size_t)GMAX * 256];

// unpack uint2 (4 halves) and accumulate into float4
__device__ __forceinline__ void acc_u2(uint2 v, float4& a) {
    float2 f0 = __half22float2(*reinterpret_cast<__half2*>(&v.x));
    float2 f1 = __half22float2(*reinterpret_cast<__half2*>(&v.y));
    a.x += f0.x; a.y += f0.y; a.z += f1.x; a.w += f1.y;
}

__device__ __forceinline__ uint2 pack_f4(float4 a, float s) {
    uint2 o;
    __half2 h0 = __floats2half2_rn(a.x * s, a.y * s);
    __half2 h1 = __floats2half2_rn(a.z * s, a.w * s);
    o.x = *reinterpret_cast<uint32_t*>(&h0);
    o.y = *reinterpret_cast<uint32_t*>(&h1);
    return o;
}

// ---------------- degree / CSR build ----------------
__global__ void count_deg_kernel(const int* __restrict__ dst, int* counts, int E) {
    int e = blockIdx.x * blockDim.x + threadIdx.x;
    if (e < E) atomicAdd(&counts[dst[e]], 1);
}

__global__ void scan_chunk_sum(const int* __restrict__ counts, int* bsum,
                               float* __restrict__ dinv, int N) {
    __shared__ int sh[256];
    int base = blockIdx.x * CHUNK;
    int s = 0;
    for (int i = threadIdx.x; i < CHUNK; i += 256) {
        int g = base + i;
        int c = (g < N) ? counts[g] : 0;
        s += c;
        if (g < N) dinv[g] = rsqrtf((float)c + 1.0f);
    }
    sh[threadIdx.x] = s; __syncthreads();
    for (int o = 128; o > 0; o >>= 1) {
        if (threadIdx.x < o) sh[threadIdx.x] += sh[threadIdx.x + o];
        __syncthreads();
    }
    if (threadIdx.x == 0) bsum[blockIdx.x] = sh[0];
}

__global__ void scan_bsum(const int* __restrict__ bsum, int* boff, int NB) {
    __shared__ int sh[512];
    int v = (threadIdx.x < NB) ? bsum[threadIdx.x] : 0;
    sh[threadIdx.x] = v; __syncthreads();
    for (int o = 1; o < 512; o <<= 1) {
        int t = (threadIdx.x >= o) ? sh[threadIdx.x - o] : 0;
        __syncthreads();
        sh[threadIdx.x] += t;
        __syncthreads();
    }
    if (threadIdx.x < NB) boff[threadIdx.x] = sh[threadIdx.x] - v;  // exclusive
}

__global__ void scan_final(const int* __restrict__ counts, const int* __restrict__ boff,
                           int* rowptr, int* cursor, int N) {
    __shared__ int sh[CHUNK];
    int g = blockIdx.x * CHUNK + threadIdx.x;
    int v = (g < N) ? counts[g] : 0;
    sh[threadIdx.x] = v; __syncthreads();
    for (int o = 1; o < CHUNK; o <<= 1) {
        int t = (threadIdx.x >= o) ? sh[threadIdx.x - o] : 0;
        __syncthreads();
        sh[threadIdx.x] += t;
        __syncthreads();
    }
    if (g < N) {
        int excl = boff[blockIdx.x] + sh[threadIdx.x] - v;
        rowptr[g] = excl;
        cursor[g] = excl;
        if (g == N - 1) rowptr[N] = boff[blockIdx.x] + sh[threadIdx.x];
    }
}

__global__ void fill_csr_kernel(const int* __restrict__ src, const int* __restrict__ dst,
                                int* cursor, int* colidx, int E) {
    int e = blockIdx.x * blockDim.x + threadIdx.x;
    if (e < E) {
        int d = dst[e];
        int p = atomicAdd(&cursor[d], 1);
        colidx[p] = src[e];
    }
}

// ---------------- conversions ----------------
// one uint4 (8 halves) per thread: i = n*10 + c covers uint2 cols 2c, 2c+1
__global__ void conv_x_kernel(const float2* __restrict__ x2, const float* __restrict__ dinv,
                              uint4* __restrict__ xsv4, int N) {
    int i = blockIdx.x * blockDim.x + threadIdx.x;   // over N*10 uint4
    if (i >= N * 10) return;
    int n = i / 10;
    int c = i - n * 10;
    float dd = __ldg(&dinv[n]);
    const float2* row = x2 + (size_t)n * 39;
    const bool full = (c < 9);
    float2 v0 = __ldg(&row[4 * c]);
    float2 v1 = __ldg(&row[4 * c + 1]);
    float2 v2 = __ldg(&row[4 * c + 2]);
    float2 v3 = full ? __ldg(&row[4 * c + 3]) : make_float2(0.f, 0.f);
    __half2 h0 = __floats2half2_rn(v0.x * dd, v0.y * dd);
    __half2 h1 = __floats2half2_rn(v1.x * dd, v1.y * dd);
    __half2 h2 = __floats2half2_rn(v2.x * dd, v2.y * dd);
    __half2 h3 = __floats2half2_rn(v3.x * dd, v3.y * dd);
    uint4 o;
    o.x = *reinterpret_cast<uint32_t*>(&h0);
    o.y = *reinterpret_cast<uint32_t*>(&h1);
    o.z = *reinterpret_cast<uint32_t*>(&h2);
    o.w = *reinterpret_cast<uint32_t*>(&h3);
    xsv4[i] = o;
}

__global__ void conv_w_kernel(const float* __restrict__ W0, const float* __restrict__ W1,
                              __half* __restrict__ W0t, __half* __restrict__ W1t) {
    int i = blockIdx.x * blockDim.x + threadIdx.x;
    if (i < 128 * 96) {
        int n = i / 96;
        int k = i - n * 96;
        W0t[i] = (k < 78) ? __float2half_rn(W0[(size_t)k * 128 + n]) : __float2half_rn(0.0f);
    } else if (i < 128 * 96 + 128 * 128) {
        int j = i - 128 * 96;
        int n = j >> 7;
        int k = j & 127;
        W1t[j] = __float2half_rn(W1[(size_t)k * 128 + n]);
    }
}

// ---------------- agg0: ax[d] = h16( dinv[d]*(xs[d] + sum_{s} xs[s]) ), xs already *dinv ----------------
__global__ void agg0_kernel(const uint2* __restrict__ xsv, const int* __restrict__ rowptr,
                            const int* __restrict__ colidx, const float* __restrict__ dinv,
                            uint2* __restrict__ axv, int N)
{
    int w = (blockIdx.x * blockDim.x + threadIdx.x) >> 5;
    int lane = threadIdx.x & 31;
    if (w >= N) return;
    const bool act = lane < 20;

    float4 a = make_float4(0.f, 0.f, 0.f, 0.f);
    if (act) acc_u2(__ldg(&xsv[(size_t)w * 20 + lane]), a);

    int s0 = __ldg(&rowptr[w]);
    int s1 = __ldg(&rowptr[w + 1]);
    int e = s0;
    for (; e + 4 <= s1; e += 4) {
        int i0 = __ldg(&colidx[e + 0]);
        int i1 = __ldg(&colidx[e + 1]);
        int i2 = __ldg(&colidx[e + 2]);
        int i3 = __ldg(&colidx[e + 3]);
        if (act) {
            uint2 u0 = __ldg(&xsv[(size_t)i0 * 20 + lane]);
            uint2 u1 = __ldg(&xsv[(size_t)i1 * 20 + lane]);
            uint2 u2 = __ldg(&xsv[(size_t)i2 * 20 + lane]);
            uint2 u3 = __ldg(&xsv[(size_t)i3 * 20 + lane]);
            acc_u2(u0, a); acc_u2(u1, a); acc_u2(u2, a); acc_u2(u3, a);
        }
    }
    // tail: up to 3 edges, batched with predicated accumulate (duplicate loads safe)
    int rem = s1 - e;
    if (rem > 0) {
        int i0 = __ldg(&colidx[e]);
        int i1 = (rem > 1) ? __ldg(&colidx[e + 1]) : i0;
        int i2 = (rem > 2) ? __ldg(&colidx[e + 2]) : i0;
        if (act) {
            uint2 u0 = __ldg(&xsv[(size_t)i0 * 20 + lane]);
            uint2 u1 = __ldg(&xsv[(size_t)i1 * 20 + lane]);
            uint2 u2 = __ldg(&xsv[(size_t)i2 * 20 + lane]);
            acc_u2(u0, a);
            if (rem > 1) acc_u2(u1, a);
            if (rem > 2) acc_u2(u2, a);
        }
    }

    float dd = __ldg(&dinv[w]);
    if (act)
        axv[(size_t)w * 24 + lane] = pack_f4(a, dd);
    else if (lane < 24)
        axv[(size_t)w * 24 + lane] = make_uint2(0u, 0u);   // pad halves 80..95
}

// ---------------- agg1 (128-dim): ah[d] = h16( dinv[d]*(hs[d] + sum_{s} hs[s]) ), hs = h0*dinv ----------------
__global__ void agg1_kernel(const uint2* __restrict__ hsv, const int* __restrict__ rowptr,
                            const int* __restrict__ colidx, const float* __restrict__ dinv,
                            uint2* __restrict__ ahv, int N)
{
    int w = (blockIdx.x * blockDim.x + threadIdx.x) >> 5;
    int lane = threadIdx.x & 31;
    if (w >= N) return;

    float4 a = make_float4(0.f, 0.f, 0.f, 0.f);
    acc_u2(__ldg(&hsv[(size_t)w * 32 + lane]), a);

    int s0 = __ldg(&rowptr[w]);
    int s1 = __ldg(&rowptr[w + 1]);
    int e = s0;
    for (; e + 4 <= s1; e += 4) {
        int i0 = __ldg(&colidx[e + 0]);
        int i1 = __ldg(&colidx[e + 1]);
        int i2 = __ldg(&colidx[e + 2]);
        int i3 = __ldg(&colidx[e + 3]);
        uint2 u0 = __ldg(&hsv[(size_t)i0 * 32 + lane]);
        uint2 u1 = __ldg(&hsv[(size_t)i1 * 32 + lane]);
        uint2 u2 = __ldg(&hsv[(size_t)i2 * 32 + lane]);
        uint2 u3 = __ldg(&hsv[(size_t)i3 * 32 + lane]);
        acc_u2(u0, a); acc_u2(u1, a); acc_u2(u2, a); acc_u2(u3, a);
    }
    int rem = s1 - e;
    if (rem > 0) {
        int i0 = __ldg(&colidx[e]);
        int i1 = (rem > 1) ? __ldg(&colidx[e + 1]) : i0;
        int i2 = (rem > 2) ? __ldg(&colidx[e + 2]) : i0;
        uint2 u0 = __ldg(&hsv[(size_t)i0 * 32 + lane]);
        uint2 u1 = __ldg(&hsv[(size_t)i1 * 32 + lane]);
        uint2 u2 = __ldg(&hsv[(size_t)i2 * 32 + lane]);
        acc_u2(u0, a);
        if (rem > 1) acc_u2(u1, a);
        if (rem > 2) acc_u2(u2, a);
    }

    float dd = __ldg(&dinv[w]);
    ahv[(size_t)w * 32 + lane] = pack_f4(a, dd);
}

// ---------------- fp16 tensor-core GEMM (layer 0): hh = h16(relu(A@Wt^T + bias) * rowscale) ----------------
__global__ void __launch_bounds__(256, 2)
gemm_h_kernel(const __half* __restrict__ A, const __half* __restrict__ Wt,
              const float* __restrict__ bias, const float* __restrict__ rowscale,
              __half* __restrict__ out, int K)
{
    __shared__ __half As[2][128 * APAD];
    __shared__ __half Bs[2][128 * APAD];

    const int tid  = threadIdx.x;
    const int row0 = blockIdx.x * 128;
    const int lane = tid & 31;
    const int wid  = tid >> 5;
    const int gid  = lane >> 2;
    const int tig  = lane & 3;
    const int wm   = (wid & 1) * 64;
    const int wn   = (wid >> 1) * 32;

    float c[4][4][4];
#pragma unroll
    for (int i = 0; i < 4; i++)
#pragma unroll
        for (int j = 0; j < 4; j++)
#pragma unroll
            for (int r = 0; r < 4; r++) c[i][j][r] = 0.0f;

    const int KC = K >> 5;

    auto issue = [&](int kc, int buf) {
        const int k0 = kc << 5;
#pragma unroll
        for (int rpt = 0; rpt < 2; rpt++) {
            int i = tid + rpt * 256;
            int m = i >> 2, ch = i & 3;
            const __half* src = A + (size_t)(row0 + m) * K + k0 + ch * 8;
            uint32_t dst = (uint32_t)__cvta_generic_to_shared(&As[buf][m * APAD + ch * 8]);
            asm volatile("cp.async.cg.shared.global [%0], [%1], 16;" :: "r"(dst), "l"(src));
        }
#pragma unroll
        for (int rpt = 0; rpt < 2; rpt++) {
            int i = tid + rpt * 256;
            int n = i >> 2, ch = i & 3;
            const __half* src = Wt + (size_t)n * K + k0 + ch * 8;
            uint32_t dst = (uint32_t)__cvta_generic_to_shared(&Bs[buf][n * APAD + ch * 8]);
            asm volatile("cp.async.cg.shared.global [%0], [%1], 16;" :: "r"(dst), "l"(src));
        }
        asm volatile("cp.async.commit_group;" ::: "memory");
    };

    issue(0, 0);

    for (int kc = 0; kc < KC; kc++) {
        const int buf = kc & 1;
        asm volatile("cp.async.wait_group 0;" ::: "memory");
        __syncthreads();
        if (kc + 1 < KC) issue(kc + 1, buf ^ 1);

#pragma unroll
        for (int s = 0; s < 2; s++) {
            const int ks = s * 16;
            uint32_t a[4][4];
#pragma unroll
            for (int mf = 0; mf < 4; mf++) {
                const __half* ab = &As[buf][(wm + mf * 16 + gid) * APAD + ks];
                a[mf][0] = *reinterpret_cast<const uint32_t*>(&ab[2 * tig]);
                a[mf][1] = *reinterpret_cast<const uint32_t*>(&ab[8 * APAD + 2 * tig]);
                a[mf][2] = *reinterpret_cast<const uint32_t*>(&ab[2 * tig + 8]);
                a[mf][3] = *reinterpret_cast<const uint32_t*>(&ab[8 * APAD + 2 * tig + 8]);
            }
            uint32_t b[4][2];
#pragma unroll
            for (int nf = 0; nf < 4; nf++) {
                const __half* bb = &Bs[buf][(wn + nf * 8 + gid) * APAD + ks];
                b[nf][0] = *reinterpret_cast<const uint32_t*>(&bb[2 * tig]);
                b[nf][1] = *reinterpret_cast<const uint32_t*>(&bb[2 * tig + 8]);
            }
#pragma unroll
            for (int mf = 0; mf < 4; mf++)
#pragma unroll
                for (int nf = 0; nf < 4; nf++) {
                    asm volatile(
                        "mma.sync.aligned.m16n8k16.row.col.f32.f16.f16.f32 "
                        "{%0,%1,%2,%3}, {%4,%5,%6,%7}, {%8,%9}, {%0,%1,%2,%3};"
                        : "+f"(c[mf][nf][0]), "+f"(c[mf][nf][1]),
                          "+f"(c[mf][nf][2]), "+f"(c[mf][nf][3])
                        : "r"(a[mf][0]), "r"(a[mf][1]), "r"(a[mf][2]), "r"(a[mf][3]),
                          "r"(b[nf][0]), "r"(b[nf][1]));
                }
        }
        __syncthreads();
    }

    float bxv[4], byv[4];
#pragma unroll
    for (int nf = 0; nf < 4; nf++) {
        const int cc = wn + nf * 8 + 2 * tig;
        bxv[nf] = bias[cc];
        byv[nf] = bias[cc + 1];
    }
#pragma unroll
    for (int mf = 0; mf < 4; mf++) {
        const int r0 = row0 + wm + mf * 16 + gid;
        float rs0 = rowscale[r0], rs1 = rowscale[r0 + 8];
#pragma unroll
        for (int nf = 0; nf < 4; nf++) {
            const int cc = wn + nf * 8 + 2 * tig;
            __half2 v0 = __floats2half2_rn(fmaxf(c[mf][nf][0] + bxv[nf], 0.f) * rs0,
                                           fmaxf(c[mf][nf][1] + byv[nf], 0.f) * rs0);
            __half2 v1 = __floats2half2_rn(fmaxf(c[mf][nf][2] + bxv[nf], 0.f) * rs1,
                                           fmaxf(c[mf][nf][3] + byv[nf], 0.f) * rs1);
            *reinterpret_cast<__half2*>(&out[(size_t)r0 * 128 + cc]) = v0;
            *reinterpret_cast<__half2*>(&out[(size_t)(r0 + 8) * 128 + cc]) = v1;
        }
    }
}

// ---------------- fused layer-1 GEMM + global max pool ----------------
__global__ void __launch_bounds__(256, 2)
gemm_h_pool_kernel(const __half* __restrict__ A, const __half* __restrict__ Wt,
                   const float* __restrict__ bias, const int* __restrict__ batch,
                   float* __restrict__ pool, int K, int G)
{
    __shared__ __half As[2][128 * APAD];
    __shared__ __half Bs[2][128 * APAD];
    __shared__ unsigned int pool_s[4 * 128];   // up to 4 graph segments per 128-row block

    const int tid  = threadIdx.x;
    const int row0 = blockIdx.x * 128;
    const int lane = tid & 31;
    const int wid  = tid >> 5;
    const int gid  = lane >> 2;
    const int tig  = lane & 3;
    const int wm   = (wid & 1) * 64;
    const int wn   = (wid >> 1) * 32;

    for (int i = tid; i < 4 * 128; i += 256) pool_s[i] = 0u;

    float c[4][4][4];
#pragma unroll
    for (int i = 0; i < 4; i++)
#pragma unroll
        for (int j = 0; j < 4; j++)
#pragma unroll
            for (int r = 0; r < 4; r++) c[i][j][r] = 0.0f;

    const int KC = K >> 5;

    auto issue = [&](int kc, int buf) {
        const int k0 = kc << 5;
#pragma unroll
        for (int rpt = 0; rpt < 2; rpt++) {
            int i = tid + rpt * 256;
            int m = i >> 2, ch = i & 3;
            const __half* src = A + (size_t)(row0 + m) * K + k0 + ch * 8;
            uint32_t dst = (uint32_t)__cvta_generic_to_shared(&As[buf][m * APAD + ch * 8]);
            asm volatile("cp.async.cg.shared.global [%0], [%1], 16;" :: "r"(dst), "l"(src));
        }
#pragma unroll
        for (int rpt = 0; rpt < 2; rpt++) {
            int i = tid + rpt * 256;
            int n = i >> 2, ch = i & 3;
            const __half* src = Wt + (size_t)n * K + k0 + ch * 8;
            uint32_t dst = (uint32_t)__cvta_generic_to_shared(&Bs[buf][n * APAD + ch * 8]);
            asm volatile("cp.async.cg.shared.global [%0], [%1], 16;" :: "r"(dst), "l"(src));
        }
        asm volatile("cp.async.commit_group;" ::: "memory");
    };

    issue(0, 0);

    for (int kc = 0; kc < KC; kc++) {
        const int buf = kc & 1;
        asm volatile("cp.async.wait_group 0;" ::: "memory");
        __syncthreads();
        if (kc + 1 < KC) issue(kc + 1, buf ^ 1);

#pragma unroll
        for (int s = 0; s < 2; s++) {
            const int ks = s * 16;
            uint32_t a[4][4];
#pragma unroll
            for (int mf = 0; mf < 4; mf++) {
                const __half* ab = &As[buf][(wm + mf * 16 + gid) * APAD + ks];
                a[mf][0] = *reinterpret_cast<const uint32_t*>(&ab[2 * tig]);
                a[mf][1] = *reinterpret_cast<const uint32_t*>(&ab[8 * APAD + 2 * tig]);
                a[mf][2] = *reinterpret_cast<const uint32_t*>(&ab[2 * tig + 8]);
                a[mf][3] = *reinterpret_cast<const uint32_t*>(&ab[8 * APAD + 2 * tig + 8]);
            }
            uint32_t b[4][2];
#pragma unroll
            for (int nf = 0; nf < 4; nf++) {
                const __half* bb = &Bs[buf][(wn + nf * 8 + gid) * APAD + ks];
                b[nf][0] = *reinterpret_cast<const uint32_t*>(&bb[2 * tig]);
                b[nf][1] = *reinterpret_cast<const uint32_t*>(&bb[2 * tig + 8]);
            }
#pragma unroll
            for (int mf = 0; mf < 4; mf++)
#pragma unroll
                for (int nf = 0; nf < 4; nf++) {
                    asm volatile(
                        "mma.sync.aligned.m16n8k16.row.col.f32.f16.f16.f32 "
                        "{%0,%1,%2,%3}, {%4,%5,%6,%7}, {%8,%9}, {%0,%1,%2,%3};"
                        : "+f"(c[mf][nf][0]), "+f"(c[mf][nf][1]),
                          "+f"(c[mf][nf][2]), "+f"(c[mf][nf][3])
                        : "r"(a[mf][0]), "r"(a[mf][1]), "r"(a[mf][2]), "r"(a[mf][3]),
                          "r"(b[nf][0]), "r"(b[nf][1]));
                }
        }
        __syncthreads();
    }

    // epilogue: relu(acc+bias) -> per-segment smem max -> global atomicMax
    float bxv[4], byv[4];
#pragma unroll
    for (int nf = 0; nf < 4; nf++) {
        const int cc = wn + nf * 8 + 2 * tig;
        bxv[nf] = bias[cc];
        byv[nf] = bias[cc + 1];
    }
    const int gbase = __ldg(&batch[row0]);
#pragma unroll
    for (int mf = 0; mf < 4; mf++) {
        const int r0 = row0 + wm + mf * 16 + gid;
        const int seg0 = __ldg(&batch[r0]) - gbase;
        const int seg1 = __ldg(&batch[r0 + 8]) - gbase;
#pragma unroll
        for (int nf = 0; nf < 4; nf++) {
            const int cc = wn + nf * 8 + 2 * tig;
            float v00 = fmaxf(c[mf][nf][0] + bxv[nf], 0.f);
            float v01 = fmaxf(c[mf][nf][1] + byv[nf], 0.f);
            float v10 = fmaxf(c[mf][nf][2] + bxv[nf], 0.f);
            float v11 = fmaxf(c[mf][nf][3] + byv[nf], 0.f);
            atomicMax(&pool_s[seg0 * 128 + cc],     __float_as_uint(v00));
            atomicMax(&pool_s[seg0 * 128 + cc + 1], __float_as_uint(v01));
            atomicMax(&pool_s[seg1 * 128 + cc],     __float_as_uint(v10));
            atomicMax(&pool_s[seg1 * 128 + cc + 1], __float_as_uint(v11));
        }
    }
    __syncthreads();
    for (int i = tid; i < 4 * 128; i += 256) {
        int g = gbase + (i >> 7);
        unsigned int v = pool_s[i];
        if (g < G && v != 0u)
            atomicMax(reinterpret_cast<unsigned int*>(&pool[(size_t)g * 128 + (i & 127)]), v);
    }
}

// ---------------- FFMA GEMM for FF head (full fp32): out = relu(A@W + bias) ----------------
__global__ void __launch_bounds__(256, 2)
gemm_ff_kernel(const float* __restrict__ A, const float* __restrict__ W,
               const float* __restrict__ bias, float* __restrict__ out,
               int M, int K, int Nout)
{
    __shared__ float As[16 * 128];
    __shared__ float Bs[16 * 128];

    const int tid  = threadIdx.x;
    const int tx   = tid & 15;
    const int ty   = tid >> 4;
    const int row0 = blockIdx.x * 128;
    const int col0 = blockIdx.y * 128;

    float acc[8][8];
#pragma unroll
    for (int i = 0; i < 8; i++)
#pragma unroll
        for (int j = 0; j < 8; j++) acc[i][j] = 0.0f;

    const int KC = (K + 15) >> 4;
    for (int kc = 0; kc < KC; kc++) {
        const int k0 = kc << 4;
        for (int i = tid; i < 512; i += 256) {
            int m = i >> 2, kv = (i & 3) << 2;
            int row = row0 + m;
            float4 v = make_float4(0.f, 0.f, 0.f, 0.f);
            if (row < M && (k0 + kv) < K)
                v = *reinterpret_cast<const float4*>(&A[(size_t)row * K + k0 + kv]);
            As[(kv + 0) * 128 + m] = v.x;
            As[(kv + 1) * 128 + m] = v.y;
            As[(kv + 2) * 128 + m] = v.z;
            As[(kv + 3) * 128 + m] = v.w;
        }
        for (int i = tid; i < 512; i += 256) {
            int kk = i >> 5, n4 = (i & 31) << 2;
            float4 v = make_float4(0.f, 0.f, 0.f, 0.f);
            if ((k0 + kk) < K)
                v = *reinterpret_cast<const float4*>(&W[(size_t)(k0 + kk) * Nout + col0 + n4]);
            *reinterpret_cast<float4*>(&Bs[kk * 128 + n4]) = v;
        }
        __syncthreads();
#pragma unroll
        for (int kk = 0; kk < 16; kk++) {
            float4 a0 = *reinterpret_cast<const float4*>(&As[kk * 128 + ty * 8]);
            float4 a1 = *reinterpret_cast<const float4*>(&As[kk * 128 + ty * 8 + 4]);
            float4 b0 = *reinterpret_cast<const float4*>(&Bs[kk * 128 + tx * 8]);
            float4 b1 = *reinterpret_cast<const float4*>(&Bs[kk * 128 + tx * 8 + 4]);
            float av[8] = {a0.x, a0.y, a0.z, a0.w, a1.x, a1.y, a1.z, a1.w};
            float bv[8] = {b0.x, b0.y, b0.z, b0.w, b1.x, b1.y, b1.z, b1.w};
#pragma unroll
            for (int i = 0; i < 8; i++)
#pragma unroll
                for (int j = 0; j < 8; j++)
                    acc[i][j] += av[i] * bv[j];
        }
        __syncthreads();
    }

#pragma unroll
    for (int i = 0; i < 8; i++) {
        int row = row0 + ty * 8 + i;
        if (row >= M) break;
        const float4 b0 = *reinterpret_cast<const float4*>(&bias[col0 + tx * 8]);
        const float4 b1 = *reinterpret_cast<const float4*>(&bias[col0 + tx * 8 + 4]);
        float4 v0 = make_float4(fmaxf(acc[i][0] + b0.x, 0.f), fmaxf(acc[i][1] + b0.y, 0.f),
                                fmaxf(acc[i][2] + b0.z, 0.f), fmaxf(acc[i][3] + b0.w, 0.f));
        float4 v1 = make_float4(fmaxf(acc[i][4] + b1.x, 0.f), fmaxf(acc[i][5] + b1.y, 0.f),
                                fmaxf(acc[i][6] + b1.z, 0.f), fmaxf(acc[i][7] + b1.w, 0.f));
        float4* o = reinterpret_cast<float4*>(&out[(size_t)row * Nout + col0 + tx * 8]);
        o[0] = v0; o[1] = v1;
    }
}

// ---------------- launch ----------------
extern "C" void kernel_launch(void* const* d_in, const int* in_sizes, int n_in,
                              void* d_out, int out_size)
{
    const float* x     = (const float*)d_in[0];
    const int*   ei    = (const int*)d_in[1];
    const int*   batch = (const int*)d_in[2];
    const float* W0    = (const float*)d_in[3];
    const float* b0    = (const float*)d_in[4];
    const float* W1    = (const float*)d_in[5];
    const float* b1    = (const float*)d_in[6];
    const float* Wf0   = (const float*)d_in[7];
    const float* bf0   = (const float*)d_in[8];
    const float* Wf1   = (const float*)d_in[9];
    const float* bf1   = (const float*)d_in[10];
    float*       out   = (float*)d_out;

    const int F_IN = 78;
    const int N = in_sizes[0] / F_IN;
    const int E = in_sizes[1] / 2;
    const int G = out_size / HD;

    const int* src = ei;
    const int* dst = ei + E;

    int *p_counts, *p_rowptr, *p_cursor, *p_colidx, *p_bsum, *p_boff;
    float *p_dinv, *p_pool, *p_ff;
    __half *p_xs, *p_ax, *p_hh, *p_ah, *p_w0t, *p_w1t;
    cudaGetSymbolAddress((void**)&p_counts, g_counts);
    cudaGetSymbolAddress((void**)&p_rowptr, g_rowptr);
    cudaGetSymbolAddress((void**)&p_cursor, g_cursor);
    cudaGetSymbolAddress((void**)&p_colidx, g_colidx);
    cudaGetSymbolAddress((void**)&p_bsum,   g_bsum);
    cudaGetSymbolAddress((void**)&p_boff,   g_boff);
    cudaGetSymbolAddress((void**)&p_dinv,   g_dinv);
    cudaGetSymbolAddress((void**)&p_xs,     g_xs);
    cudaGetSymbolAddress((void**)&p_ax,     g_ax);
    cudaGetSymbolAddress((void**)&p_hh,     g_hh);
    cudaGetSymbolAddress((void**)&p_ah,     g_ah);
    cudaGetSymbolAddress((void**)&p_w0t,    g_w0t);
    cudaGetSymbolAddress((void**)&p_w1t,    g_w1t);
    cudaGetSymbolAddress((void**)&p_pool,   g_pool);
    cudaGetSymbolAddress((void**)&p_ff,     g_ff);

    // side stream + events (created once on the uncaptured correctness call)
    static cudaStream_t s2 = nullptr;
    static cudaEvent_t ev_entry = nullptr, ev_dinv = nullptr, ev_conv = nullptr;
    if (!s2) {
        cudaStreamCreateWithFlags(&s2, cudaStreamNonBlocking);
        cudaEventCreateWithFlags(&ev_entry, cudaEventDisableTiming);
        cudaEventCreateWithFlags(&ev_dinv,  cudaEventDisableTiming);
        cudaEventCreateWithFlags(&ev_conv,  cudaEventDisableTiming);
    }

    const int TB = 256;
    int gE = (E + TB - 1) / TB;
    int NB = (N + CHUNK - 1) / CHUNK;
    int gW = (N * 32 + TB - 1) / TB;   // warp-per-node grids

    // ---- fork: side stream does weight conversion + pool zero-init ----
    cudaEventRecord(ev_entry, 0);
    cudaStreamWaitEvent(s2, ev_entry, 0);
    conv_w_kernel<<<(128 * 96 + 128 * 128 + TB - 1) / TB, TB, 0, s2>>>(W0, W1, p_w0t, p_w1t);
    cudaMemsetAsync(p_pool, 0, (size_t)G * HD * sizeof(float), s2);

    // ---- main stream: CSR build + norm ----
    cudaMemsetAsync(p_counts, 0, (size_t)N * sizeof(int));
    count_deg_kernel<<<gE, TB>>>(dst, p_counts, E);
    scan_chunk_sum<<<NB, 256>>>(p_counts, p_bsum, p_dinv, N);
    cudaEventRecord(ev_dinv, 0);              // dinv ready -> conv_x can start on s2
    cudaStreamWaitEvent(s2, ev_dinv, 0);
    conv_x_kernel<<<(N * 10 + TB - 1) / TB, TB, 0, s2>>>(
        (const float2*)x, p_dinv, (uint4*)p_xs, N);
    cudaEventRecord(ev_conv, s2);

    scan_bsum<<<1, 512>>>(p_bsum, p_boff, NB);
    scan_final<<<NB, CHUNK>>>(p_counts, p_boff, p_rowptr, p_cursor, N);
    fill_csr_kernel<<<gE, TB>>>(src, dst, p_cursor, p_colidx, E);

    // ---- join: agg0 needs xs (s2) + CSR (main); gemm needs w0t (s2) ----
    cudaStreamWaitEvent(0, ev_conv, 0);

    // ---- layer 0: aggregate-then-transform; GEMM stores h0*dinv ----
    agg0_kernel<<<gW, TB>>>((const uint2*)p_xs, p_rowptr, p_colidx, p_dinv, (uint2*)p_ax, N);
    gemm_h_kernel<<<N / 128, TB>>>(p_ax, p_w0t, b0, p_dinv, p_hh, 96);

    // ---- layer 1: agg + fused GEMM/max-pool (h1 never materialized) ----
    agg1_kernel<<<gW, TB>>>((const uint2*)p_hh, p_rowptr, p_colidx, p_dinv, (uint2*)p_ah, N);
    gemm_h_pool_kernel<<<N / 128, TB>>>(p_ah, p_w1t, b1, batch, p_pool, 128, G);

    // ---- FF head (fp32) ----
    {
        dim3 grid((G + 127) / 128, 2);
        gemm_ff_kernel<<<grid, TB>>>(p_pool, Wf0, bf0, p_ff, G, HD, 256);
    }
    {
        dim3 grid((G + 127) / 128, 1);
        gemm_ff_kernel<<<grid, TB>>>(p_ff, Wf1, bf1, out, G, 256, HD);
    }
}